// round 1
// baseline (speedup 1.0000x reference)
#include <cuda_runtime.h>
#include <cstdint>
#include <cstddef>

// ---------------- problem constants ----------------
#define BATCH   64
#define SEQL    720      // L
#define ENC     512      // C
#define NROWS   (BATCH*ENC)       // 32768
#define NFREQ   361               // rfft bins
#define SPECW   (2*NFREQ)         // 722 : [Re | Im]
#define H_FREQ  64
#define H1      128
#define H2      256
#define PREDL   720

// ---------------- scratch (device globals; no allocs allowed) ----------------
__device__ float g_basis[SEQL*SPECW];        // DFT matrix [l][f]: cos | -sin
__device__ float g_cosl[SEQL];
__device__ float g_sinl[SEQL];
__device__ float g_xt  [(size_t)NROWS*SEQL]; // x channel-major (b,c,l)
__device__ float g_spec[(size_t)NROWS*SPECW];
__device__ float g_filt[(size_t)NROWS*SEQL];
__device__ float g_h   [(size_t)NROWS*H_FREQ];
__device__ float g_z1  [(size_t)NROWS*H1];
__device__ float g_z   [(size_t)NROWS*H2];
__device__ float g_t   [(size_t)NROWS*H2];
__device__ float g_tT  [(size_t)BATCH*H2*ENC];
__device__ float g_cm  [(size_t)BATCH*H2*ENC];
__device__ float g_cT  [(size_t)NROWS*H2];
__device__ float g_pred[(size_t)NROWS*PREDL];

// ---------------- LUT / basis fill ----------------
__global__ void fill_basis(float* __restrict__ basis, float* __restrict__ cosl,
                           float* __restrict__ sinl) {
    int idx = blockIdx.x * blockDim.x + threadIdx.x;
    if (idx < SEQL) {
        double s, c;
        sincospi((double)(2 * idx) / (double)SEQL, &s, &c);
        cosl[idx] = (float)c;
        sinl[idx] = (float)s;
    }
    if (idx < SEQL * SPECW) {
        int l = idx / SPECW, f = idx % SPECW;
        int ff = (f < NFREQ) ? f : f - NFREQ;
        int a = (l * ff) % SEQL;
        double s, c;
        sincospi((double)(2 * a) / (double)SEQL, &s, &c);
        basis[idx] = (f < NFREQ) ? (float)c : (float)(-s);
    }
}

// ---------------- batched transpose (B,R,C) -> (B,C,R) ----------------
__global__ void transpose_batched(const float* __restrict__ in, float* __restrict__ out,
                                  int R, int C) {
    __shared__ float tile[32][33];
    int b = blockIdx.z;
    int c0 = blockIdx.x * 32, r0 = blockIdx.y * 32;
    const float* pin = in + (size_t)b * R * C;
    float* pout = out + (size_t)b * R * C;
    int tx = threadIdx.x, ty = threadIdx.y;
#pragma unroll
    for (int j = 0; j < 32; j += 8) {
        int r = r0 + ty + j, c = c0 + tx;
        if (r < R && c < C) tile[ty + j][tx] = pin[(size_t)r * C + c];
    }
    __syncthreads();
#pragma unroll
    for (int j = 0; j < 32; j += 8) {
        int c = c0 + ty + j, r = r0 + tx;
        if (c < C && r < R) pout[(size_t)c * R + r] = tile[tx][ty + j];
    }
}

// src: (B,C,L) channel-major; out: (B,L,C); if xin != null, out = xin - src^T
__global__ void transpose_sub(const float* __restrict__ src, const float* __restrict__ xin,
                              float* __restrict__ out, int L, int C) {
    __shared__ float tile[32][33];
    int b = blockIdx.z;
    int l0 = blockIdx.x * 32, c0 = blockIdx.y * 32;
    const float* ps = src + (size_t)b * C * L;
#pragma unroll
    for (int j = 0; j < 32; j += 8) {
        int c = c0 + threadIdx.y + j, l = l0 + threadIdx.x;
        if (c < C && l < L) tile[threadIdx.y + j][threadIdx.x] = ps[(size_t)c * L + l];
    }
    __syncthreads();
    size_t ob = (size_t)b * L * C;
#pragma unroll
    for (int j = 0; j < 32; j += 8) {
        int l = l0 + threadIdx.y + j, c = c0 + threadIdx.x;
        if (l < L && c < C) {
            float v = tile[threadIdx.x][threadIdx.y + j];
            if (xin) v = xin[ob + (size_t)l * C + c] - v;
            out[ob + (size_t)l * C + c] = v;
        }
    }
}

// ---------------- generic SGEMM with fused epilogues ----------------
// MODE 0: C = A@B + bias
// MODE 1: C = relu(A@B + bias)
// MODE 2: C = relu(A@B + bias + Cin)
// MODE 3: C = Cin + relu(A@B + bias)
template <int MODE>
__global__ void __launch_bounds__(256) gemm_k(
    const float* __restrict__ A, int lda,
    const float* __restrict__ B, int ldb,
    const float* __restrict__ bias,
    const float* __restrict__ Cin, int ldcin,
    float* __restrict__ C, int ldc,
    int M, int N, int K) {
    __shared__ float As[64][17];
    __shared__ float Bs[16][64];
    int tid = threadIdx.x;
    int tx = tid & 15, ty = tid >> 4;
    int m0 = blockIdx.y * 64, n0 = blockIdx.x * 64;
    float acc[4][4] = {};

    for (int k0 = 0; k0 < K; k0 += 16) {
#pragma unroll
        for (int i = 0; i < 4; i++) {
            int idx = tid + i * 256;
            int m = idx >> 4, kk = idx & 15;
            int gm = m0 + m, gk = k0 + kk;
            As[m][kk] = (gm < M && gk < K) ? A[(size_t)gm * lda + gk] : 0.f;
        }
#pragma unroll
        for (int i = 0; i < 4; i++) {
            int idx = tid + i * 256;
            int kk = idx >> 6, n = idx & 63;
            int gk = k0 + kk, gn = n0 + n;
            Bs[kk][n] = (gk < K && gn < N) ? B[(size_t)gk * ldb + gn] : 0.f;
        }
        __syncthreads();
        int ty4 = ty * 4, tx4 = tx * 4;
#pragma unroll
        for (int kk = 0; kk < 16; kk++) {
            float a0 = As[ty4 + 0][kk], a1 = As[ty4 + 1][kk];
            float a2 = As[ty4 + 2][kk], a3 = As[ty4 + 3][kk];
            float4 bv = *reinterpret_cast<const float4*>(&Bs[kk][tx4]);
            acc[0][0] += a0 * bv.x; acc[0][1] += a0 * bv.y; acc[0][2] += a0 * bv.z; acc[0][3] += a0 * bv.w;
            acc[1][0] += a1 * bv.x; acc[1][1] += a1 * bv.y; acc[1][2] += a1 * bv.z; acc[1][3] += a1 * bv.w;
            acc[2][0] += a2 * bv.x; acc[2][1] += a2 * bv.y; acc[2][2] += a2 * bv.z; acc[2][3] += a2 * bv.w;
            acc[3][0] += a3 * bv.x; acc[3][1] += a3 * bv.y; acc[3][2] += a3 * bv.z; acc[3][3] += a3 * bv.w;
        }
        __syncthreads();
    }

#pragma unroll
    for (int i = 0; i < 4; i++) {
        int gm = m0 + ty * 4 + i;
        if (gm >= M) continue;
#pragma unroll
        for (int j = 0; j < 4; j++) {
            int gn = n0 + tx * 4 + j;
            if (gn >= N) continue;
            float v = acc[i][j];
            if (bias) v += bias[gn];
            if (MODE == 1) v = fmaxf(v, 0.f);
            else if (MODE == 2) { v += Cin[(size_t)gm * ldcin + gn]; v = fmaxf(v, 0.f); }
            else if (MODE == 3) { v = Cin[(size_t)gm * ldcin + gn] + fmaxf(v, 0.f); }
            C[(size_t)gm * ldc + gn] = v;
        }
    }
}

// ---------------- per-row top-k + sparse irfft reconstruction ----------------
__global__ void __launch_bounds__(256) topk_reconstruct(
    const float* __restrict__ spec, const int* __restrict__ kptr,
    const float* __restrict__ cosl, const float* __restrict__ sinl,
    float* __restrict__ filt) {
    int row = blockIdx.x;
    const float* re = spec + (size_t)row * SPECW;
    const float* im = re + NFREQ;

    __shared__ float smag[NFREQ];
    __shared__ float scos[SEQL], ssin[SEQL];
    __shared__ int   sfreq[32];
    __shared__ float sre[32], sim[32], sw[32];
    __shared__ float rmax[8];
    __shared__ int   ridx[8];

    int tid = threadIdx.x;
    for (int i = tid; i < NFREQ; i += 256) {
        float r = re[i], m = im[i];
        smag[i] = r * r + m * m;
    }
    for (int i = tid; i < SEQL; i += 256) { scos[i] = cosl[i]; ssin[i] = sinl[i]; }
    int k = *kptr;
    if (k > 32) k = 32;
    if (k < 0) k = 0;
    __syncthreads();

    for (int it = 0; it < k; it++) {
        float best = -1.f; int bidx = 0x7fffffff;
        for (int i = tid; i < NFREQ; i += 256) {
            float v = smag[i];
            if (v > best || (v == best && i < bidx)) { best = v; bidx = i; }
        }
#pragma unroll
        for (int o = 16; o > 0; o >>= 1) {
            float ov = __shfl_down_sync(0xffffffffu, best, o);
            int   oi = __shfl_down_sync(0xffffffffu, bidx, o);
            if (ov > best || (ov == best && oi < bidx)) { best = ov; bidx = oi; }
        }
        if ((tid & 31) == 0) { rmax[tid >> 5] = best; ridx[tid >> 5] = bidx; }
        __syncthreads();
        if (tid == 0) {
            float b2 = -1.f; int bi = 0x7fffffff;
#pragma unroll
            for (int w = 0; w < 8; w++) {
                if (rmax[w] > b2 || (rmax[w] == b2 && ridx[w] < bi)) { b2 = rmax[w]; bi = ridx[w]; }
            }
            sfreq[it] = bi;
            smag[bi] = -2.f;                 // exclude from further iterations
            sre[it] = re[bi];
            sim[it] = im[bi];
            sw[it] = (bi == 0 || bi == NFREQ - 1) ? 1.f : 2.f;
        }
        __syncthreads();
    }

    const float scale = 1.f / (float)SEQL;
    for (int t = tid; t < SEQL; t += 256) {
        float acc = 0.f;
        for (int j = 0; j < k; j++) {
            int f = sfreq[j];
            int a = (f * t) % SEQL;
            acc += sw[j] * (sre[j] * scos[a] - sim[j] * ssin[a]);
        }
        filt[(size_t)row * SEQL + t] = acc * scale;
    }
}

// ---------------- host launch ----------------
extern "C" void kernel_launch(void* const* d_in, const int* in_sizes, int n_in,
                              void* d_out, int out_size) {
    const float* x      = (const float*)d_in[0];
    const float* w_freq = (const float*)d_in[1];
    const float* b_freq = (const float*)d_in[2];
    const float* w_all1 = (const float*)d_in[3];
    const float* b_all1 = (const float*)d_in[4];
    const float* w_all2 = (const float*)d_in[5];
    const float* b_all2 = (const float*)d_in[6];
    const float* w_time = (const float*)d_in[7];
    const float* b_time = (const float*)d_in[8];
    const float* w_chan = (const float*)d_in[9];
    const float* b_chan = (const float*)d_in[10];
    const float* w_proj = (const float*)d_in[11];
    const float* b_proj = (const float*)d_in[12];
    const int*   kptr   = (const int*)d_in[13];
    float* out = (float*)d_out;
    size_t half = (size_t)out_size / 2;

    float *basis, *cosl, *sinl, *xt, *spec, *filt, *h, *z1, *z, *t, *tT, *cm, *cT, *pred;
    cudaGetSymbolAddress((void**)&basis, g_basis);
    cudaGetSymbolAddress((void**)&cosl, g_cosl);
    cudaGetSymbolAddress((void**)&sinl, g_sinl);
    cudaGetSymbolAddress((void**)&xt, g_xt);
    cudaGetSymbolAddress((void**)&spec, g_spec);
    cudaGetSymbolAddress((void**)&filt, g_filt);
    cudaGetSymbolAddress((void**)&h, g_h);
    cudaGetSymbolAddress((void**)&z1, g_z1);
    cudaGetSymbolAddress((void**)&z, g_z);
    cudaGetSymbolAddress((void**)&t, g_t);
    cudaGetSymbolAddress((void**)&tT, g_tT);
    cudaGetSymbolAddress((void**)&cm, g_cm);
    cudaGetSymbolAddress((void**)&cT, g_cT);
    cudaGetSymbolAddress((void**)&pred, g_pred);

    dim3 tb(32, 8);

    // 0) DFT basis + cos/sin LUTs
    fill_basis<<<(SEQL * SPECW + 255) / 256, 256>>>(basis, cosl, sinl);

    // 1) x (b,L,C) -> xt (b,C,L)
    transpose_batched<<<dim3(ENC / 32, (SEQL + 31) / 32, BATCH), tb>>>(x, xt, SEQL, ENC);

    // 2) spec = xt @ [cos|-sin]   (32768 x 722)
    gemm_k<0><<<dim3((SPECW + 63) / 64, NROWS / 64), 256>>>(
        xt, SEQL, basis, SPECW, nullptr, nullptr, 0, spec, SPECW, NROWS, SPECW, SEQL);

    // 3) per-row top-k + sparse irfft -> filt (b,c,l), includes 1/L
    topk_reconstruct<<<NROWS, 256>>>(spec, kptr, cosl, sinl, filt);

    // 4) residual = x - filt^T  -> first half of d_out
    transpose_sub<<<dim3((SEQL + 31) / 32, ENC / 32, BATCH), tb>>>(filt, x, out, SEQL, ENC);

    // 5) h = relu(filt @ w_freq + b_freq)
    gemm_k<1><<<dim3(1, NROWS / 64), 256>>>(
        filt, SEQL, w_freq, H_FREQ, b_freq, nullptr, 0, h, H_FREQ, NROWS, H_FREQ, SEQL);

    // 6) z1 = h @ w_all1[0:64] + b_all1 ; then z1 = relu(xt @ w_all1[64:] + z1)
    gemm_k<0><<<dim3(H1 / 64, NROWS / 64), 256>>>(
        h, H_FREQ, w_all1, H1, b_all1, nullptr, 0, z1, H1, NROWS, H1, H_FREQ);
    gemm_k<2><<<dim3(H1 / 64, NROWS / 64), 256>>>(
        xt, SEQL, w_all1 + (size_t)H_FREQ * H1, H1, nullptr, z1, H1, z1, H1, NROWS, H1, SEQL);

    // 7) z = z1 @ w_all2 + b_all2
    gemm_k<0><<<dim3(H2 / 64, NROWS / 64), 256>>>(
        z1, H1, w_all2, H2, b_all2, nullptr, 0, z, H2, NROWS, H2, H1);

    // 8) t = z + relu(z @ w_time + b_time)
    gemm_k<3><<<dim3(H2 / 64, NROWS / 64), 256>>>(
        z, H2, w_time, H2, b_time, z, H2, t, H2, NROWS, H2, H2);

    // 9) t (b,C,H2) -> tT (b,H2,C)
    transpose_batched<<<dim3(H2 / 32, ENC / 32, BATCH), tb>>>(t, tT, ENC, H2);

    // 10) cm = tT + relu(tT @ w_chan + b_chan)   (rows = b*H2 = 16384, N=K=512)
    gemm_k<3><<<dim3(ENC / 64, (BATCH * H2) / 64), 256>>>(
        tT, ENC, w_chan, ENC, b_chan, tT, ENC, cm, ENC, BATCH * H2, ENC, ENC);

    // 11) cm (b,H2,C) -> cT (b,C,H2)
    transpose_batched<<<dim3(ENC / 32, H2 / 32, BATCH), tb>>>(cm, cT, H2, ENC);

    // 12) pred = cT @ w_proj + b_proj   (32768 x 720)
    gemm_k<0><<<dim3((PREDL + 63) / 64, NROWS / 64), 256>>>(
        cT, H2, w_proj, PREDL, b_proj, nullptr, 0, pred, PREDL, NROWS, PREDL, H2);

    // 13) pred (b,c,l) -> (b,l,c) into second half of d_out
    transpose_sub<<<dim3((PREDL + 31) / 32, ENC / 32, BATCH), tb>>>(
        pred, nullptr, out + half, PREDL, ENC);
}

// round 4
// speedup vs baseline: 1.3070x; 1.3070x over previous
#include <cuda_runtime.h>
#include <cstdint>
#include <cstddef>

// ---------------- problem constants ----------------
#define BATCH   64
#define SEQL    720      // L
#define ENC     512      // C
#define NROWS   (BATCH*ENC)       // 32768
#define NFREQ   361               // rfft bins
#define SPECW   (2*NFREQ)         // 722 : [Re | Im]
#define H_FREQ  64
#define H1      128
#define H2      256
#define PREDL   720

// ---------------- scratch (device globals; no allocs allowed) ----------------
__device__ float g_basis[SEQL*SPECW];        // DFT matrix [l][f]: cos | -sin
__device__ float g_cosl[SEQL];
__device__ float g_sinl[SEQL];
__device__ float g_xt  [(size_t)NROWS*SEQL]; // x channel-major (b,c,l)
__device__ float g_spec[(size_t)NROWS*SPECW];
__device__ float g_filt[(size_t)NROWS*SEQL];
__device__ float g_h   [(size_t)NROWS*H_FREQ];
__device__ float g_z1  [(size_t)NROWS*H1];
__device__ float g_z   [(size_t)NROWS*H2];
__device__ float g_t   [(size_t)NROWS*H2];
__device__ float g_tT  [(size_t)BATCH*H2*ENC];
__device__ float g_cm  [(size_t)BATCH*H2*ENC];
__device__ float g_cT  [(size_t)NROWS*H2];
__device__ float g_pred[(size_t)NROWS*PREDL];

// ---------------- LUT / basis fill ----------------
__global__ void fill_basis(float* __restrict__ basis, float* __restrict__ cosl,
                           float* __restrict__ sinl) {
    int idx = blockIdx.x * blockDim.x + threadIdx.x;
    if (idx < SEQL) {
        double s, c;
        sincospi((double)(2 * idx) / (double)SEQL, &s, &c);
        cosl[idx] = (float)c;
        sinl[idx] = (float)s;
    }
    if (idx < SEQL * SPECW) {
        int l = idx / SPECW, f = idx % SPECW;
        int ff = (f < NFREQ) ? f : f - NFREQ;
        int a = (l * ff) % SEQL;
        double s, c;
        sincospi((double)(2 * a) / (double)SEQL, &s, &c);
        basis[idx] = (f < NFREQ) ? (float)c : (float)(-s);
    }
}

// ---------------- batched transpose (B,R,C) -> (B,C,R) ----------------
__global__ void transpose_batched(const float* __restrict__ in, float* __restrict__ out,
                                  int R, int C) {
    __shared__ float tile[32][33];
    int b = blockIdx.z;
    int c0 = blockIdx.x * 32, r0 = blockIdx.y * 32;
    const float* pin = in + (size_t)b * R * C;
    float* pout = out + (size_t)b * R * C;
    int tx = threadIdx.x, ty = threadIdx.y;
#pragma unroll
    for (int j = 0; j < 32; j += 8) {
        int r = r0 + ty + j, c = c0 + tx;
        if (r < R && c < C) tile[ty + j][tx] = pin[(size_t)r * C + c];
    }
    __syncthreads();
#pragma unroll
    for (int j = 0; j < 32; j += 8) {
        int c = c0 + ty + j, r = r0 + tx;
        if (c < C && r < R) pout[(size_t)c * R + r] = tile[tx][ty + j];
    }
}

// src: (B,C,L) channel-major; out: (B,L,C); if xin != null, out = xin - src^T
__global__ void transpose_sub(const float* __restrict__ src, const float* __restrict__ xin,
                              float* __restrict__ out, int L, int C) {
    __shared__ float tile[32][33];
    int b = blockIdx.z;
    int l0 = blockIdx.x * 32, c0 = blockIdx.y * 32;
    const float* ps = src + (size_t)b * C * L;
#pragma unroll
    for (int j = 0; j < 32; j += 8) {
        int c = c0 + threadIdx.y + j, l = l0 + threadIdx.x;
        if (c < C && l < L) tile[threadIdx.y + j][threadIdx.x] = ps[(size_t)c * L + l];
    }
    __syncthreads();
    size_t ob = (size_t)b * L * C;
#pragma unroll
    for (int j = 0; j < 32; j += 8) {
        int l = l0 + threadIdx.y + j, c = c0 + threadIdx.x;
        if (l < L && c < C) {
            float v = tile[threadIdx.x][threadIdx.y + j];
            if (xin) v = xin[ob + (size_t)l * C + c] - v;
            out[ob + (size_t)l * C + c] = v;
        }
    }
}

// ---------------- small-N SGEMM (64x64x16), kept for N=64 ----------------
// MODE 0: C = A@B + bias ; 1: relu ; 2: relu(+Cin) ; 3: Cin + relu
template <int MODE>
__global__ void __launch_bounds__(256) gemm_k(
    const float* __restrict__ A, int lda,
    const float* __restrict__ B, int ldb,
    const float* __restrict__ bias,
    const float* __restrict__ Cin, int ldcin,
    float* __restrict__ C, int ldc,
    int M, int N, int K) {
    __shared__ float As[64][17];
    __shared__ float Bs[16][64];
    int tid = threadIdx.x;
    int tx = tid & 15, ty = tid >> 4;
    int m0 = blockIdx.y * 64, n0 = blockIdx.x * 64;
    float acc[4][4] = {};

    for (int k0 = 0; k0 < K; k0 += 16) {
#pragma unroll
        for (int i = 0; i < 4; i++) {
            int idx = tid + i * 256;
            int m = idx >> 4, kk = idx & 15;
            int gm = m0 + m, gk = k0 + kk;
            As[m][kk] = (gm < M && gk < K) ? A[(size_t)gm * lda + gk] : 0.f;
        }
#pragma unroll
        for (int i = 0; i < 4; i++) {
            int idx = tid + i * 256;
            int kk = idx >> 6, n = idx & 63;
            int gk = k0 + kk, gn = n0 + n;
            Bs[kk][n] = (gk < K && gn < N) ? B[(size_t)gk * ldb + gn] : 0.f;
        }
        __syncthreads();
        int ty4 = ty * 4, tx4 = tx * 4;
#pragma unroll
        for (int kk = 0; kk < 16; kk++) {
            float a0 = As[ty4 + 0][kk], a1 = As[ty4 + 1][kk];
            float a2 = As[ty4 + 2][kk], a3 = As[ty4 + 3][kk];
            float4 bv = *reinterpret_cast<const float4*>(&Bs[kk][tx4]);
            acc[0][0] += a0 * bv.x; acc[0][1] += a0 * bv.y; acc[0][2] += a0 * bv.z; acc[0][3] += a0 * bv.w;
            acc[1][0] += a1 * bv.x; acc[1][1] += a1 * bv.y; acc[1][2] += a1 * bv.z; acc[1][3] += a1 * bv.w;
            acc[2][0] += a2 * bv.x; acc[2][1] += a2 * bv.y; acc[2][2] += a2 * bv.z; acc[2][3] += a2 * bv.w;
            acc[3][0] += a3 * bv.x; acc[3][1] += a3 * bv.y; acc[3][2] += a3 * bv.z; acc[3][3] += a3 * bv.w;
        }
        __syncthreads();
    }

#pragma unroll
    for (int i = 0; i < 4; i++) {
        int gm = m0 + ty * 4 + i;
        if (gm >= M) continue;
#pragma unroll
        for (int j = 0; j < 4; j++) {
            int gn = n0 + tx * 4 + j;
            if (gn >= N) continue;
            float v = acc[i][j];
            if (bias) v += bias[gn];
            if (MODE == 1) v = fmaxf(v, 0.f);
            else if (MODE == 2) { v += Cin[(size_t)gm * ldcin + gn]; v = fmaxf(v, 0.f); }
            else if (MODE == 3) { v = Cin[(size_t)gm * ldcin + gn] + fmaxf(v, 0.f); }
            C[(size_t)gm * ldc + gn] = v;
        }
    }
}

// ---------------- big SGEMM: 128x128x8 tiles, 8x8 per thread ----------------
// Requirements: M % 128 == 0, K % 8 == 0, K >= 16. N guarded.
template <int MODE>
__global__ void __launch_bounds__(256) gemm128(
    const float* __restrict__ A, int lda,
    const float* __restrict__ B, int ldb,
    const float* __restrict__ bias,
    const float* __restrict__ Cin, int ldcin,
    float* __restrict__ C, int ldc,
    int M, int N, int K) {
    __shared__ float As[8][132];   // [k][m], padded: conflict-free scatter stores
    __shared__ float Bs[8][128];   // [k][n]
    const int tid = threadIdx.x;
    const int m0 = blockIdx.y * 128, n0 = blockIdx.x * 128;

    // A staging: row = tid>>1 (0..127), 4 consecutive k at (tid&1)*4
    const int arow = tid >> 1, acol = (tid & 1) * 4;
    // B staging: k = tid>>5 (0..7), 4 consecutive n at (tid&31)*4
    const int bk = tid >> 5, bn = (tid & 31) * 4;
    // compute fragment bases (each thread: m in {tm..tm+3, tm+64..}, n likewise)
    const int tn = (tid & 15) * 4;
    const int tm = (tid >> 4) * 4;

    float acc[2][4][2][4] = {};   // [mi][i][ni][j]

    // prefetch first tile into registers
    float4 aP = *reinterpret_cast<const float4*>(&A[(size_t)(m0 + arow) * lda + acol]);
    float bP0, bP1, bP2, bP3;
    {
        const float* Brow = &B[(size_t)bk * ldb];
        int n = n0 + bn;
        bP0 = (n + 0 < N) ? Brow[n + 0] : 0.f;
        bP1 = (n + 1 < N) ? Brow[n + 1] : 0.f;
        bP2 = (n + 2 < N) ? Brow[n + 2] : 0.f;
        bP3 = (n + 3 < N) ? Brow[n + 3] : 0.f;
    }

    for (int k0 = 0; k0 < K; k0 += 8) {
        As[acol + 0][arow] = aP.x;
        As[acol + 1][arow] = aP.y;
        As[acol + 2][arow] = aP.z;
        As[acol + 3][arow] = aP.w;
        *reinterpret_cast<float4*>(&Bs[bk][bn]) = make_float4(bP0, bP1, bP2, bP3);
        __syncthreads();

        if (k0 + 8 < K) {
            aP = *reinterpret_cast<const float4*>(&A[(size_t)(m0 + arow) * lda + (k0 + 8 + acol)]);
            const float* Brow = &B[(size_t)(k0 + 8 + bk) * ldb];
            int n = n0 + bn;
            bP0 = (n + 0 < N) ? Brow[n + 0] : 0.f;
            bP1 = (n + 1 < N) ? Brow[n + 1] : 0.f;
            bP2 = (n + 2 < N) ? Brow[n + 2] : 0.f;
            bP3 = (n + 3 < N) ? Brow[n + 3] : 0.f;
        }

#pragma unroll
        for (int kk = 0; kk < 8; kk++) {
            float af[8], bf[8];
            *reinterpret_cast<float4*>(&af[0]) = *reinterpret_cast<const float4*>(&As[kk][tm]);
            *reinterpret_cast<float4*>(&af[4]) = *reinterpret_cast<const float4*>(&As[kk][tm + 64]);
            *reinterpret_cast<float4*>(&bf[0]) = *reinterpret_cast<const float4*>(&Bs[kk][tn]);
            *reinterpret_cast<float4*>(&bf[4]) = *reinterpret_cast<const float4*>(&Bs[kk][tn + 64]);
#pragma unroll
            for (int mi = 0; mi < 2; mi++)
#pragma unroll
                for (int i = 0; i < 4; i++)
#pragma unroll
                    for (int ni = 0; ni < 2; ni++)
#pragma unroll
                        for (int j = 0; j < 4; j++)
                            acc[mi][i][ni][j] = fmaf(af[mi * 4 + i], bf[ni * 4 + j], acc[mi][i][ni][j]);
        }
        __syncthreads();
    }

#pragma unroll
    for (int mi = 0; mi < 2; mi++)
#pragma unroll
        for (int i = 0; i < 4; i++) {
            int gm = m0 + tm + mi * 64 + i;
#pragma unroll
            for (int ni = 0; ni < 2; ni++)
#pragma unroll
                for (int j = 0; j < 4; j++) {
                    int gn = n0 + tn + ni * 64 + j;
                    if (gn >= N) continue;
                    float v = acc[mi][i][ni][j];
                    if (bias) v += bias[gn];
                    if (MODE == 1) v = fmaxf(v, 0.f);
                    else if (MODE == 2) { v += Cin[(size_t)gm * ldcin + gn]; v = fmaxf(v, 0.f); }
                    else if (MODE == 3) { v = Cin[(size_t)gm * ldcin + gn] + fmaxf(v, 0.f); }
                    C[(size_t)gm * ldc + gn] = v;
                }
        }
}

// ---------------- per-row top-k (warp-private) + sparse irfft ----------------
__global__ void __launch_bounds__(256) topk_reconstruct(
    const float* __restrict__ spec, const int* __restrict__ kptr,
    const float* __restrict__ cosl, const float* __restrict__ sinl,
    float* __restrict__ filt) {
    int row = blockIdx.x;
    const float* re = spec + (size_t)row * SPECW;
    const float* im = re + NFREQ;

    __shared__ float scos[SEQL], ssin[SEQL];
    __shared__ int   sfreq[32];
    __shared__ float sre[32], sim[32];   // pre-scaled by weight/L
    __shared__ int   sk;

    int tid = threadIdx.x;
    for (int i = tid; i < SEQL; i += 256) { scos[i] = cosl[i]; ssin[i] = sinl[i]; }

    if (tid < 32) {
        int lane = tid;
        float mre[12], mim[12], mag[12];
#pragma unroll
        for (int j = 0; j < 12; j++) {
            int idx = lane + 32 * j;
            if (idx < NFREQ) {
                float r = re[idx], m = im[idx];
                mre[j] = r; mim[j] = m; mag[j] = r * r + m * m;
            } else { mre[j] = 0.f; mim[j] = 0.f; mag[j] = -1.f; }
        }
        int k = *kptr;
        if (k > 32) k = 32;
        if (k < 0) k = 0;
        if (lane == 0) sk = k;
        const float scale = 1.f / (float)SEQL;
        for (int it = 0; it < k; it++) {
            float best = -1.f; int bslot = 0;
#pragma unroll
            for (int j = 0; j < 12; j++)
                if (mag[j] > best) { best = mag[j]; bslot = j; }   // ties -> lowest idx
            int bidx = lane + 32 * bslot;
#pragma unroll
            for (int o = 16; o > 0; o >>= 1) {
                float ov = __shfl_xor_sync(0xffffffffu, best, o);
                int   oi = __shfl_xor_sync(0xffffffffu, bidx, o);
                if (ov > best || (ov == best && oi < bidx)) { best = ov; bidx = oi; }
            }
            // winner's owning lane records and retires it
            if ((bidx & 31) == lane) {
                int j = bidx >> 5;
                float w = (bidx == 0 || bidx == NFREQ - 1) ? scale : 2.f * scale;
                sfreq[it] = bidx;
                sre[it] = mre[j] * w;
                sim[it] = mim[j] * w;
                mag[j] = -2.f;
            }
        }
    }
    __syncthreads();

    int k = sk;
    float* outp = filt + (size_t)row * SEQL;
    for (int t = tid; t < SEQL; t += 256) {
        float acc = 0.f;
        for (int j = 0; j < k; j++) {
            unsigned a = ((unsigned)sfreq[j] * (unsigned)t) % SEQL;
            acc = fmaf(sre[j], scos[a], acc);
            acc = fmaf(-sim[j], ssin[a], acc);
        }
        outp[t] = acc;
    }
}

// ---------------- host launch ----------------
extern "C" void kernel_launch(void* const* d_in, const int* in_sizes, int n_in,
                              void* d_out, int out_size) {
    const float* x      = (const float*)d_in[0];
    const float* w_freq = (const float*)d_in[1];
    const float* b_freq = (const float*)d_in[2];
    const float* w_all1 = (const float*)d_in[3];
    const float* b_all1 = (const float*)d_in[4];
    const float* w_all2 = (const float*)d_in[5];
    const float* b_all2 = (const float*)d_in[6];
    const float* w_time = (const float*)d_in[7];
    const float* b_time = (const float*)d_in[8];
    const float* w_chan = (const float*)d_in[9];
    const float* b_chan = (const float*)d_in[10];
    const float* w_proj = (const float*)d_in[11];
    const float* b_proj = (const float*)d_in[12];
    const int*   kptr   = (const int*)d_in[13];
    float* out = (float*)d_out;
    size_t half = (size_t)out_size / 2;

    float *basis, *cosl, *sinl, *xt, *spec, *filt, *h, *z1, *z, *t, *tT, *cm, *cT, *pred;
    cudaGetSymbolAddress((void**)&basis, g_basis);
    cudaGetSymbolAddress((void**)&cosl, g_cosl);
    cudaGetSymbolAddress((void**)&sinl, g_sinl);
    cudaGetSymbolAddress((void**)&xt, g_xt);
    cudaGetSymbolAddress((void**)&spec, g_spec);
    cudaGetSymbolAddress((void**)&filt, g_filt);
    cudaGetSymbolAddress((void**)&h, g_h);
    cudaGetSymbolAddress((void**)&z1, g_z1);
    cudaGetSymbolAddress((void**)&z, g_z);
    cudaGetSymbolAddress((void**)&t, g_t);
    cudaGetSymbolAddress((void**)&tT, g_tT);
    cudaGetSymbolAddress((void**)&cm, g_cm);
    cudaGetSymbolAddress((void**)&cT, g_cT);
    cudaGetSymbolAddress((void**)&pred, g_pred);

    dim3 tb(32, 8);

    // 0) DFT basis + cos/sin LUTs
    fill_basis<<<(SEQL * SPECW + 255) / 256, 256>>>(basis, cosl, sinl);

    // 1) x (b,L,C) -> xt (b,C,L)
    transpose_batched<<<dim3(ENC / 32, (SEQL + 31) / 32, BATCH), tb>>>(x, xt, SEQL, ENC);

    // 2) spec = xt @ [cos|-sin]   (32768 x 722, K=720)
    gemm128<0><<<dim3((SPECW + 127) / 128, NROWS / 128), 256>>>(
        xt, SEQL, basis, SPECW, nullptr, nullptr, 0, spec, SPECW, NROWS, SPECW, SEQL);

    // 3) per-row top-k + sparse irfft -> filt (b,c,l), includes 1/L and weights
    topk_reconstruct<<<NROWS, 256>>>(spec, kptr, cosl, sinl, filt);

    // 4) residual = x - filt^T  -> first half of d_out
    transpose_sub<<<dim3((SEQL + 31) / 32, ENC / 32, BATCH), tb>>>(filt, x, out, SEQL, ENC);

    // 5) h = relu(filt @ w_freq + b_freq)   (N=64 -> 64-wide tiles)
    gemm_k<1><<<dim3(1, NROWS / 64), 256>>>(
        filt, SEQL, w_freq, H_FREQ, b_freq, nullptr, 0, h, H_FREQ, NROWS, H_FREQ, SEQL);

    // 6) z1 = h @ w_all1[0:64] + b_all1 ; then z1 = relu(xt @ w_all1[64:] + z1)
    gemm128<0><<<dim3(1, NROWS / 128), 256>>>(
        h, H_FREQ, w_all1, H1, b_all1, nullptr, 0, z1, H1, NROWS, H1, H_FREQ);
    gemm128<2><<<dim3(1, NROWS / 128), 256>>>(
        xt, SEQL, w_all1 + (size_t)H_FREQ * H1, H1, nullptr, z1, H1, z1, H1, NROWS, H1, SEQL);

    // 7) z = z1 @ w_all2 + b_all2
    gemm128<0><<<dim3(H2 / 128, NROWS / 128), 256>>>(
        z1, H1, w_all2, H2, b_all2, nullptr, 0, z, H2, NROWS, H2, H1);

    // 8) t = z + relu(z @ w_time + b_time)
    gemm128<3><<<dim3(H2 / 128, NROWS / 128), 256>>>(
        z, H2, w_time, H2, b_time, z, H2, t, H2, NROWS, H2, H2);

    // 9) t (b,C,H2) -> tT (b,H2,C)
    transpose_batched<<<dim3(H2 / 32, ENC / 32, BATCH), tb>>>(t, tT, ENC, H2);

    // 10) cm = tT + relu(tT @ w_chan + b_chan)   (rows = b*H2 = 16384, N=K=512)
    gemm128<3><<<dim3(ENC / 128, (BATCH * H2) / 128), 256>>>(
        tT, ENC, w_chan, ENC, b_chan, tT, ENC, cm, ENC, BATCH * H2, ENC, ENC);

    // 11) cm (b,H2,C) -> cT (b,C,H2)
    transpose_batched<<<dim3(ENC / 32, H2 / 32, BATCH), tb>>>(cm, cT, H2, ENC);

    // 12) pred = cT @ w_proj + b_proj   (32768 x 720, K=256)
    gemm128<0><<<dim3((PREDL + 127) / 128, NROWS / 128), 256>>>(
        cT, H2, w_proj, PREDL, b_proj, nullptr, 0, pred, PREDL, NROWS, PREDL, H2);

    // 13) pred (b,c,l) -> (b,l,c) into second half of d_out
    transpose_sub<<<dim3((PREDL + 31) / 32, ENC / 32, BATCH), tb>>>(
        pred, nullptr, out + half, PREDL, ENC);
}

// round 9
// speedup vs baseline: 1.3848x; 1.0595x over previous
#include <cuda_runtime.h>
#include <cstdint>
#include <cstddef>

// ---------------- problem constants ----------------
#define BATCH   64
#define SEQL    720      // L
#define ENC     512      // C
#define NROWS   (BATCH*ENC)       // 32768
#define NFREQ   361               // rfft bins
#define SPECW   (2*NFREQ)         // 722 : [Re | Im]
#define H_FREQ  64
#define H1      128
#define H2      256
#define PREDL   720

// ---------------- scratch (device globals; no allocs allowed) ----------------
__device__ float g_basis[SEQL*SPECW];        // DFT matrix [l][f]: cos | -sin
__device__ float g_cosl[SEQL];
__device__ float g_sinl[SEQL];
__device__ float g_xt  [(size_t)NROWS*SEQL]; // x channel-major (b,c,l)
__device__ float g_spec[(size_t)NROWS*SPECW];
__device__ float g_filt[(size_t)NROWS*SEQL];
__device__ float g_h   [(size_t)NROWS*H_FREQ];
__device__ float g_z1  [(size_t)NROWS*H1];
__device__ float g_z   [(size_t)NROWS*H2];
__device__ float g_t   [(size_t)NROWS*H2];
__device__ float g_tT  [(size_t)BATCH*H2*ENC];
__device__ float g_cm  [(size_t)BATCH*H2*ENC];
__device__ float g_cT  [(size_t)NROWS*H2];
__device__ float g_pred[(size_t)NROWS*PREDL];

// ---------------- LUT / basis fill ----------------
__global__ void fill_basis(float* __restrict__ basis, float* __restrict__ cosl,
                           float* __restrict__ sinl) {
    int idx = blockIdx.x * blockDim.x + threadIdx.x;
    if (idx < SEQL) {
        double s, c;
        sincospi((double)(2 * idx) / (double)SEQL, &s, &c);
        cosl[idx] = (float)c;
        sinl[idx] = (float)s;
    }
    if (idx < SEQL * SPECW) {
        int l = idx / SPECW, f = idx % SPECW;
        int ff = (f < NFREQ) ? f : f - NFREQ;
        int a = (l * ff) % SEQL;
        double s, c;
        sincospi((double)(2 * a) / (double)SEQL, &s, &c);
        basis[idx] = (f < NFREQ) ? (float)c : (float)(-s);
    }
}

// ---------------- batched transpose (B,R,C) -> (B,C,R) ----------------
__global__ void transpose_batched(const float* __restrict__ in, float* __restrict__ out,
                                  int R, int C) {
    __shared__ float tile[32][33];
    int b = blockIdx.z;
    int c0 = blockIdx.x * 32, r0 = blockIdx.y * 32;
    const float* pin = in + (size_t)b * R * C;
    float* pout = out + (size_t)b * R * C;
    int tx = threadIdx.x, ty = threadIdx.y;
#pragma unroll
    for (int j = 0; j < 32; j += 8) {
        int r = r0 + ty + j, c = c0 + tx;
        if (r < R && c < C) tile[ty + j][tx] = pin[(size_t)r * C + c];
    }
    __syncthreads();
#pragma unroll
    for (int j = 0; j < 32; j += 8) {
        int c = c0 + ty + j, r = r0 + tx;
        if (c < C && r < R) pout[(size_t)c * R + r] = tile[tx][ty + j];
    }
}

// src: (B,C,L) channel-major; out: (B,L,C); if xin != null, out = xin - src^T
__global__ void transpose_sub(const float* __restrict__ src, const float* __restrict__ xin,
                              float* __restrict__ out, int L, int C) {
    __shared__ float tile[32][33];
    int b = blockIdx.z;
    int l0 = blockIdx.x * 32, c0 = blockIdx.y * 32;
    const float* ps = src + (size_t)b * C * L;
#pragma unroll
    for (int j = 0; j < 32; j += 8) {
        int c = c0 + threadIdx.y + j, l = l0 + threadIdx.x;
        if (c < C && l < L) tile[threadIdx.y + j][threadIdx.x] = ps[(size_t)c * L + l];
    }
    __syncthreads();
    size_t ob = (size_t)b * L * C;
#pragma unroll
    for (int j = 0; j < 32; j += 8) {
        int l = l0 + threadIdx.y + j, c = c0 + threadIdx.x;
        if (l < L && c < C) {
            float v = tile[threadIdx.x][threadIdx.y + j];
            if (xin) v = xin[ob + (size_t)l * C + c] - v;
            out[ob + (size_t)l * C + c] = v;
        }
    }
}

// ---------------- fp32 SGEMM: 128x128x8 tiles, 8x8 per thread ----------------
// Used ONLY for the spectrum GEMM (top-k selection needs full fp32 accuracy).
// Requirements: M % 128 == 0, K % 8 == 0, K >= 16. N guarded.
template <int MODE>
__global__ void __launch_bounds__(256) gemm128(
    const float* __restrict__ A, int lda,
    const float* __restrict__ B, int ldb,
    const float* __restrict__ bias,
    const float* __restrict__ Cin, int ldcin,
    float* __restrict__ C, int ldc,
    int M, int N, int K) {
    __shared__ float As[8][132];   // [k][m]
    __shared__ float Bs[8][128];   // [k][n]
    const int tid = threadIdx.x;
    const int m0 = blockIdx.y * 128, n0 = blockIdx.x * 128;

    const int arow = tid >> 1, acol = (tid & 1) * 4;
    const int bk = tid >> 5, bn = (tid & 31) * 4;
    const int tn = (tid & 15) * 4;
    const int tm = (tid >> 4) * 4;

    float acc[2][4][2][4] = {};

    float4 aP = *reinterpret_cast<const float4*>(&A[(size_t)(m0 + arow) * lda + acol]);
    float bP0, bP1, bP2, bP3;
    {
        const float* Brow = &B[(size_t)bk * ldb];
        int n = n0 + bn;
        bP0 = (n + 0 < N) ? Brow[n + 0] : 0.f;
        bP1 = (n + 1 < N) ? Brow[n + 1] : 0.f;
        bP2 = (n + 2 < N) ? Brow[n + 2] : 0.f;
        bP3 = (n + 3 < N) ? Brow[n + 3] : 0.f;
    }

    for (int k0 = 0; k0 < K; k0 += 8) {
        As[acol + 0][arow] = aP.x;
        As[acol + 1][arow] = aP.y;
        As[acol + 2][arow] = aP.z;
        As[acol + 3][arow] = aP.w;
        *reinterpret_cast<float4*>(&Bs[bk][bn]) = make_float4(bP0, bP1, bP2, bP3);
        __syncthreads();

        if (k0 + 8 < K) {
            aP = *reinterpret_cast<const float4*>(&A[(size_t)(m0 + arow) * lda + (k0 + 8 + acol)]);
            const float* Brow = &B[(size_t)(k0 + 8 + bk) * ldb];
            int n = n0 + bn;
            bP0 = (n + 0 < N) ? Brow[n + 0] : 0.f;
            bP1 = (n + 1 < N) ? Brow[n + 1] : 0.f;
            bP2 = (n + 2 < N) ? Brow[n + 2] : 0.f;
            bP3 = (n + 3 < N) ? Brow[n + 3] : 0.f;
        }

#pragma unroll
        for (int kk = 0; kk < 8; kk++) {
            float af[8], bf[8];
            *reinterpret_cast<float4*>(&af[0]) = *reinterpret_cast<const float4*>(&As[kk][tm]);
            *reinterpret_cast<float4*>(&af[4]) = *reinterpret_cast<const float4*>(&As[kk][tm + 64]);
            *reinterpret_cast<float4*>(&bf[0]) = *reinterpret_cast<const float4*>(&Bs[kk][tn]);
            *reinterpret_cast<float4*>(&bf[4]) = *reinterpret_cast<const float4*>(&Bs[kk][tn + 64]);
#pragma unroll
            for (int mi = 0; mi < 2; mi++)
#pragma unroll
                for (int i = 0; i < 4; i++)
#pragma unroll
                    for (int ni = 0; ni < 2; ni++)
#pragma unroll
                        for (int j = 0; j < 4; j++)
                            acc[mi][i][ni][j] = fmaf(af[mi * 4 + i], bf[ni * 4 + j], acc[mi][i][ni][j]);
        }
        __syncthreads();
    }

#pragma unroll
    for (int mi = 0; mi < 2; mi++)
#pragma unroll
        for (int i = 0; i < 4; i++) {
            int gm = m0 + tm + mi * 64 + i;
#pragma unroll
            for (int ni = 0; ni < 2; ni++)
#pragma unroll
                for (int j = 0; j < 4; j++) {
                    int gn = n0 + tn + ni * 64 + j;
                    if (gn >= N) continue;
                    float v = acc[mi][i][ni][j];
                    if (bias) v += bias[gn];
                    if (MODE == 1) v = fmaxf(v, 0.f);
                    else if (MODE == 2) { v += Cin[(size_t)gm * ldcin + gn]; v = fmaxf(v, 0.f); }
                    else if (MODE == 3) { v = Cin[(size_t)gm * ldcin + gn] + fmaxf(v, 0.f); }
                    C[(size_t)gm * ldc + gn] = v;
                }
        }
}

// ---------------- tf32 helpers ----------------
__device__ __forceinline__ void split_tf32(float x, uint32_t& hi, uint32_t& lo) {
    uint32_t h;
    asm("cvt.rna.tf32.f32 %0, %1;" : "=r"(h) : "f"(x));
    float r = x - __uint_as_float(h);
    uint32_t l;
    asm("cvt.rna.tf32.f32 %0, %1;" : "=r"(l) : "f"(r));
    hi = h; lo = l;
}

__device__ __forceinline__ void mma_tf32(float* d, const uint32_t* a, const uint32_t* b) {
    asm volatile(
        "mma.sync.aligned.m16n8k8.row.col.f32.tf32.tf32.f32 "
        "{%0,%1,%2,%3}, {%4,%5,%6,%7}, {%8,%9}, {%0,%1,%2,%3};\n"
        : "+f"(d[0]), "+f"(d[1]), "+f"(d[2]), "+f"(d[3])
        : "r"(a[0]), "r"(a[1]), "r"(a[2]), "r"(a[3]), "r"(b[0]), "r"(b[1]));
}

// ---------------- tensor-core GEMM: 128M x 64N block, 3x-tf32 split ----------------
// Used for all non-selection-critical GEMMs (error ~1e-5 << 1e-3 budget).
// Requires M % 128 == 0, K % 16 == 0, lda % 4 == 0. N guarded.
// MODE 0: C = A@B + bias ; 1: relu ; 2: relu(+Cin) ; 3: Cin + relu
template <int MODE>
__global__ void __launch_bounds__(256) gemm_tc(
    const float* __restrict__ A, int lda,
    const float* __restrict__ B, int ldb,
    const float* __restrict__ bias,
    const float* __restrict__ Cin, int ldcin,
    float* __restrict__ C, int ldc,
    int M, int N, int K) {
    __shared__ uint32_t As_hi[16][136];   // [k][m]
    __shared__ uint32_t As_lo[16][136];
    __shared__ uint32_t Bs_hi[16][72];    // [k][n]
    __shared__ uint32_t Bs_lo[16][72];

    const int tid = threadIdx.x;
    const int m0 = blockIdx.y * 128, n0 = blockIdx.x * 64;
    const int lane = tid & 31, warp = tid >> 5;
    const int wm = warp & 3, wn = warp >> 2;       // 4x2 warp grid
    const int m0w = wm * 32, n0w = wn * 32;        // 32x32 warp tile
    const int kq = lane & 3, gq = lane >> 2;

    const int arow = tid >> 1, ak = (tid & 1) * 8;
    const int bk = tid >> 4, bn = (tid & 15) * 4;

    float acc[2][4][4];
#pragma unroll
    for (int i = 0; i < 2; i++)
#pragma unroll
        for (int j = 0; j < 4; j++)
#pragma unroll
            for (int q = 0; q < 4; q++) acc[i][j][q] = 0.f;

    float4 aP0 = *reinterpret_cast<const float4*>(&A[(size_t)(m0 + arow) * lda + ak]);
    float4 aP1 = *reinterpret_cast<const float4*>(&A[(size_t)(m0 + arow) * lda + ak + 4]);
    float bP[4];
    {
        const float* Brow = &B[(size_t)bk * ldb];
#pragma unroll
        for (int i = 0; i < 4; i++) { int n = n0 + bn + i; bP[i] = (n < N) ? Brow[n] : 0.f; }
    }

    for (int k0 = 0; k0 < K; k0 += 16) {
        {
            float av[8] = {aP0.x, aP0.y, aP0.z, aP0.w, aP1.x, aP1.y, aP1.z, aP1.w};
#pragma unroll
            for (int i = 0; i < 8; i++) {
                uint32_t h, l; split_tf32(av[i], h, l);
                As_hi[ak + i][arow] = h; As_lo[ak + i][arow] = l;
            }
#pragma unroll
            for (int i = 0; i < 4; i++) {
                uint32_t h, l; split_tf32(bP[i], h, l);
                Bs_hi[bk][bn + i] = h; Bs_lo[bk][bn + i] = l;
            }
        }
        __syncthreads();

        if (k0 + 16 < K) {
            aP0 = *reinterpret_cast<const float4*>(&A[(size_t)(m0 + arow) * lda + (k0 + 16 + ak)]);
            aP1 = *reinterpret_cast<const float4*>(&A[(size_t)(m0 + arow) * lda + (k0 + 16 + ak + 4)]);
            const float* Brow = &B[(size_t)(k0 + 16 + bk) * ldb];
#pragma unroll
            for (int i = 0; i < 4; i++) { int n = n0 + bn + i; bP[i] = (n < N) ? Brow[n] : 0.f; }
        }

#pragma unroll
        for (int ks = 0; ks < 16; ks += 8) {
            uint32_t ah[2][4], al[2][4], bh[4][2], bl[4][2];
#pragma unroll
            for (int mi = 0; mi < 2; mi++) {
                int m = m0w + mi * 16 + gq;
                ah[mi][0] = As_hi[ks + kq][m];     ah[mi][1] = As_hi[ks + kq][m + 8];
                ah[mi][2] = As_hi[ks + kq + 4][m]; ah[mi][3] = As_hi[ks + kq + 4][m + 8];
                al[mi][0] = As_lo[ks + kq][m];     al[mi][1] = As_lo[ks + kq][m + 8];
                al[mi][2] = As_lo[ks + kq + 4][m]; al[mi][3] = As_lo[ks + kq + 4][m + 8];
            }
#pragma unroll
            for (int ni = 0; ni < 4; ni++) {
                int n = n0w + ni * 8 + gq;
                bh[ni][0] = Bs_hi[ks + kq][n]; bh[ni][1] = Bs_hi[ks + kq + 4][n];
                bl[ni][0] = Bs_lo[ks + kq][n]; bl[ni][1] = Bs_lo[ks + kq + 4][n];
            }
#pragma unroll
            for (int mi = 0; mi < 2; mi++)
#pragma unroll
                for (int ni = 0; ni < 4; ni++) {
                    mma_tf32(acc[mi][ni], ah[mi], bh[ni]);
                    mma_tf32(acc[mi][ni], al[mi], bh[ni]);
                    mma_tf32(acc[mi][ni], ah[mi], bl[ni]);
                }
        }
        __syncthreads();
    }

#pragma unroll
    for (int mi = 0; mi < 2; mi++)
#pragma unroll
        for (int ni = 0; ni < 4; ni++)
#pragma unroll
            for (int hf = 0; hf < 2; hf++) {
                int gm = m0 + m0w + mi * 16 + gq + hf * 8;
                int gn = n0 + n0w + ni * 8 + kq * 2;
                float v0 = acc[mi][ni][hf * 2 + 0];
                float v1 = acc[mi][ni][hf * 2 + 1];
                if (bias) { v0 += bias[gn]; if (gn + 1 < N) v1 += bias[gn + 1]; }
                if (MODE == 1) { v0 = fmaxf(v0, 0.f); v1 = fmaxf(v1, 0.f); }
                else if (MODE == 2) {
                    v0 += Cin[(size_t)gm * ldcin + gn];
                    if (gn + 1 < N) v1 += Cin[(size_t)gm * ldcin + gn + 1];
                    v0 = fmaxf(v0, 0.f); v1 = fmaxf(v1, 0.f);
                } else if (MODE == 3) {
                    v0 = Cin[(size_t)gm * ldcin + gn] + fmaxf(v0, 0.f);
                    if (gn + 1 < N) v1 = Cin[(size_t)gm * ldcin + gn + 1] + fmaxf(v1, 0.f);
                }
                if (gn < N)     C[(size_t)gm * ldc + gn]     = v0;
                if (gn + 1 < N) C[(size_t)gm * ldc + gn + 1] = v1;
            }
}

// ---------------- per-row top-k (warp-private) + sparse irfft ----------------
__global__ void __launch_bounds__(256) topk_reconstruct(
    const float* __restrict__ spec, const int* __restrict__ kptr,
    const float* __restrict__ cosl, const float* __restrict__ sinl,
    float* __restrict__ filt) {
    int row = blockIdx.x;
    const float* re = spec + (size_t)row * SPECW;
    const float* im = re + NFREQ;

    __shared__ float2 slut[SEQL];        // (cos, sin) interleaved
    __shared__ int   sfreq[32];
    __shared__ float sre[32], sim[32];   // pre-scaled by weight/L
    __shared__ int   sk;

    int tid = threadIdx.x;
    for (int i = tid; i < SEQL; i += 256) slut[i] = make_float2(cosl[i], sinl[i]);

    if (tid < 32) {
        int lane = tid;
        float mre[12], mim[12], mag[12];
#pragma unroll
        for (int j = 0; j < 12; j++) {
            int idx = lane + 32 * j;
            if (idx < NFREQ) {
                float r = re[idx], m = im[idx];
                mre[j] = r; mim[j] = m; mag[j] = r * r + m * m;
            } else { mre[j] = 0.f; mim[j] = 0.f; mag[j] = -1.f; }
        }
        int k = *kptr;
        if (k > 32) k = 32;
        if (k < 0) k = 0;
        if (lane == 0) sk = k;
        const float scale = 1.f / (float)SEQL;
        for (int it = 0; it < k; it++) {
            float best = -1.f; int bslot = 0;
#pragma unroll
            for (int j = 0; j < 12; j++)
                if (mag[j] > best) { best = mag[j]; bslot = j; }
            int bidx = lane + 32 * bslot;
#pragma unroll
            for (int o = 16; o > 0; o >>= 1) {
                float ov = __shfl_xor_sync(0xffffffffu, best, o);
                int   oi = __shfl_xor_sync(0xffffffffu, bidx, o);
                if (ov > best || (ov == best && oi < bidx)) { best = ov; bidx = oi; }
            }
            if ((bidx & 31) == lane) {
                int j = bidx >> 5;
                float w = (bidx == 0 || bidx == NFREQ - 1) ? scale : 2.f * scale;
                sfreq[it] = bidx;
                sre[it] = mre[j] * w;
                sim[it] = mim[j] * w;
                mag[j] = -2.f;
            }
        }
    }
    __syncthreads();

    int k = sk;
    float* outp = filt + (size_t)row * SEQL;
    if (tid < 240) {
        int t0 = 3 * tid;
        float acc0 = 0.f, acc1 = 0.f, acc2 = 0.f;
        for (int j = 0; j < k; j++) {
            int f = sfreq[j];
            float r = sre[j], m = sim[j];
            int a0 = (f * t0) % SEQL;
            int a1 = a0 + f; if (a1 >= SEQL) a1 -= SEQL;
            int a2 = a1 + f; if (a2 >= SEQL) a2 -= SEQL;
            float2 p0 = slut[a0], p1 = slut[a1], p2 = slut[a2];
            acc0 = fmaf(r, p0.x, fmaf(-m, p0.y, acc0));
            acc1 = fmaf(r, p1.x, fmaf(-m, p1.y, acc1));
            acc2 = fmaf(r, p2.x, fmaf(-m, p2.y, acc2));
        }
        outp[t0 + 0] = acc0;
        outp[t0 + 1] = acc1;
        outp[t0 + 2] = acc2;
    }
}

// ---------------- host launch ----------------
extern "C" void kernel_launch(void* const* d_in, const int* in_sizes, int n_in,
                              void* d_out, int out_size) {
    const float* x      = (const float*)d_in[0];
    const float* w_freq = (const float*)d_in[1];
    const float* b_freq = (const float*)d_in[2];
    const float* w_all1 = (const float*)d_in[3];
    const float* b_all1 = (const float*)d_in[4];
    const float* w_all2 = (const float*)d_in[5];
    const float* b_all2 = (const float*)d_in[6];
    const float* w_time = (const float*)d_in[7];
    const float* b_time = (const float*)d_in[8];
    const float* w_chan = (const float*)d_in[9];
    const float* b_chan = (const float*)d_in[10];
    const float* w_proj = (const float*)d_in[11];
    const float* b_proj = (const float*)d_in[12];
    const int*   kptr   = (const int*)d_in[13];
    float* out = (float*)d_out;
    size_t half = (size_t)out_size / 2;

    float *basis, *cosl, *sinl, *xt, *spec, *filt, *h, *z1, *z, *t, *tT, *cm, *cT, *pred;
    cudaGetSymbolAddress((void**)&basis, g_basis);
    cudaGetSymbolAddress((void**)&cosl, g_cosl);
    cudaGetSymbolAddress((void**)&sinl, g_sinl);
    cudaGetSymbolAddress((void**)&xt, g_xt);
    cudaGetSymbolAddress((void**)&spec, g_spec);
    cudaGetSymbolAddress((void**)&filt, g_filt);
    cudaGetSymbolAddress((void**)&h, g_h);
    cudaGetSymbolAddress((void**)&z1, g_z1);
    cudaGetSymbolAddress((void**)&z, g_z);
    cudaGetSymbolAddress((void**)&t, g_t);
    cudaGetSymbolAddress((void**)&tT, g_tT);
    cudaGetSymbolAddress((void**)&cm, g_cm);
    cudaGetSymbolAddress((void**)&cT, g_cT);
    cudaGetSymbolAddress((void**)&pred, g_pred);

    dim3 tb(32, 8);

    // 0) DFT basis + cos/sin LUTs
    fill_basis<<<(SEQL * SPECW + 255) / 256, 256>>>(basis, cosl, sinl);

    // 1) x (b,L,C) -> xt (b,C,L)
    transpose_batched<<<dim3(ENC / 32, (SEQL + 31) / 32, BATCH), tb>>>(x, xt, SEQL, ENC);

    // 2) spec = xt @ [cos|-sin]   (32768 x 722, K=720) -- fp32: selection-critical
    gemm128<0><<<dim3((SPECW + 127) / 128, NROWS / 128), 256>>>(
        xt, SEQL, basis, SPECW, nullptr, nullptr, 0, spec, SPECW, NROWS, SPECW, SEQL);

    // 3) per-row top-k + sparse irfft -> filt (b,c,l), includes 1/L and weights
    topk_reconstruct<<<NROWS, 256>>>(spec, kptr, cosl, sinl, filt);

    // 4) residual = x - filt^T  -> first half of d_out
    transpose_sub<<<dim3((SEQL + 31) / 32, ENC / 32, BATCH), tb>>>(filt, x, out, SEQL, ENC);

    // 5) h = relu(filt @ w_freq + b_freq)   (N=64, K=720)
    gemm_tc<1><<<dim3(1, NROWS / 128), 256>>>(
        filt, SEQL, w_freq, H_FREQ, b_freq, nullptr, 0, h, H_FREQ, NROWS, H_FREQ, SEQL);

    // 6) z1 = h @ w_all1[0:64] + b_all1 ; then z1 = relu(xt @ w_all1[64:] + z1)
    gemm_tc<0><<<dim3(H1 / 64, NROWS / 128), 256>>>(
        h, H_FREQ, w_all1, H1, b_all1, nullptr, 0, z1, H1, NROWS, H1, H_FREQ);
    gemm_tc<2><<<dim3(H1 / 64, NROWS / 128), 256>>>(
        xt, SEQL, w_all1 + (size_t)H_FREQ * H1, H1, nullptr, z1, H1, z1, H1, NROWS, H1, SEQL);

    // 7) z = z1 @ w_all2 + b_all2
    gemm_tc<0><<<dim3(H2 / 64, NROWS / 128), 256>>>(
        z1, H1, w_all2, H2, b_all2, nullptr, 0, z, H2, NROWS, H2, H1);

    // 8) t = z + relu(z @ w_time + b_time)
    gemm_tc<3><<<dim3(H2 / 64, NROWS / 128), 256>>>(
        z, H2, w_time, H2, b_time, z, H2, t, H2, NROWS, H2, H2);

    // 9) t (b,C,H2) -> tT (b,H2,C)
    transpose_batched<<<dim3(H2 / 32, ENC / 32, BATCH), tb>>>(t, tT, ENC, H2);

    // 10) cm = tT + relu(tT @ w_chan + b_chan)   (rows = b*H2 = 16384, N=K=512)
    gemm_tc<3><<<dim3(ENC / 64, (BATCH * H2) / 128), 256>>>(
        tT, ENC, w_chan, ENC, b_chan, tT, ENC, cm, ENC, BATCH * H2, ENC, ENC);

    // 11) cm (b,H2,C) -> cT (b,C,H2)
    transpose_batched<<<dim3(ENC / 32, H2 / 32, BATCH), tb>>>(cm, cT, H2, ENC);

    // 12) pred = cT @ w_proj + b_proj   (32768 x 720, K=256)
    gemm_tc<0><<<dim3((PREDL + 63) / 64, NROWS / 128), 256>>>(
        cT, H2, w_proj, PREDL, b_proj, nullptr, 0, pred, PREDL, NROWS, PREDL, H2);

    // 13) pred (b,c,l) -> (b,l,c) into second half of d_out
    transpose_sub<<<dim3((PREDL + 31) / 32, ENC / 32, BATCH), tb>>>(
        pred, nullptr, out + half, PREDL, ENC);
}

// round 10
// speedup vs baseline: 2.0869x; 1.5070x over previous
#include <cuda_runtime.h>
#include <cuda_bf16.h>
#include <cstdint>
#include <cstddef>

// ---------------- problem constants ----------------
#define BATCH   64
#define SEQL    720      // L = 16 * 45
#define ENC     512      // C
#define NROWS   (BATCH*ENC)       // 32768
#define NFREQ   361               // rfft bins
#define H_FREQ  64
#define H1      128
#define H2      256
#define PREDL   720

#define L1F     16       // first CT factor
#define L2F     45       // second CT factor
#define K48     48       // padded inner K
#define N90     90       // [cos|-sin] for DFT45

// ---------------- scratch (device globals; no allocs allowed) ----------------
__device__ float g_basis45[K48*N90];          // DFT45 matrix, rows 45..47 zero
__device__ float g_cosl[SEQL];
__device__ float g_sinl[SEQL];
__device__ float g_xt  [(size_t)NROWS*SEQL];  // x channel-major (b,c,l)
__device__ float g_xt2 [(size_t)NROWS*L1F*K48]; // CT-permuted rows [row*16+l1][l2(48)]
__device__ float g_spec2[(size_t)NROWS*L1F*N90]; // stage-1 partial spectra
__device__ float g_filt[(size_t)NROWS*SEQL];
__device__ float g_h   [(size_t)NROWS*H_FREQ];
__device__ float g_z1  [(size_t)NROWS*H1];
__device__ float g_z   [(size_t)NROWS*H2];
__device__ float g_t   [(size_t)NROWS*H2];
__device__ float g_tT  [(size_t)BATCH*H2*ENC];
__device__ float g_cm  [(size_t)BATCH*H2*ENC];
__device__ float g_cT  [(size_t)NROWS*H2];
__device__ float g_pred[(size_t)NROWS*PREDL];

// ---------------- LUT / basis fill ----------------
__global__ void fill_luts(float* __restrict__ basis45, float* __restrict__ cosl,
                          float* __restrict__ sinl) {
    int idx = blockIdx.x * blockDim.x + threadIdx.x;
    if (idx < SEQL) {
        double s, c;
        sincospi((double)(2 * idx) / (double)SEQL, &s, &c);
        cosl[idx] = (float)c;
        sinl[idx] = (float)s;
    }
    if (idx < K48 * N90) {
        int l2 = idx / N90, cidx = idx % N90;
        int g = (cidx < L2F) ? cidx : cidx - L2F;
        float v = 0.f;
        if (l2 < L2F) {
            int a = (g * l2) % L2F;
            double s, c;
            sincospi((double)(2 * a) / (double)L2F, &s, &c);
            v = (cidx < L2F) ? (float)c : (float)(-s);
        }
        basis45[idx] = v;
    }
}

// ---------------- batched transpose (B,R,C) -> (B,C,R) ----------------
__global__ void transpose_batched(const float* __restrict__ in, float* __restrict__ out,
                                  int R, int C) {
    __shared__ float tile[32][33];
    int b = blockIdx.z;
    int c0 = blockIdx.x * 32, r0 = blockIdx.y * 32;
    const float* pin = in + (size_t)b * R * C;
    float* pout = out + (size_t)b * R * C;
    int tx = threadIdx.x, ty = threadIdx.y;
#pragma unroll
    for (int j = 0; j < 32; j += 8) {
        int r = r0 + ty + j, c = c0 + tx;
        if (r < R && c < C) tile[ty + j][tx] = pin[(size_t)r * C + c];
    }
    __syncthreads();
#pragma unroll
    for (int j = 0; j < 32; j += 8) {
        int c = c0 + ty + j, r = r0 + tx;
        if (c < C && r < R) pout[(size_t)c * R + r] = tile[tx][ty + j];
    }
}

// src: (B,C,L) channel-major; out: (B,L,C); if xin != null, out = xin - src^T
__global__ void transpose_sub(const float* __restrict__ src, const float* __restrict__ xin,
                              float* __restrict__ out, int L, int C) {
    __shared__ float tile[32][33];
    int b = blockIdx.z;
    int l0 = blockIdx.x * 32, c0 = blockIdx.y * 32;
    const float* ps = src + (size_t)b * C * L;
#pragma unroll
    for (int j = 0; j < 32; j += 8) {
        int c = c0 + threadIdx.y + j, l = l0 + threadIdx.x;
        if (c < C && l < L) tile[threadIdx.y + j][threadIdx.x] = ps[(size_t)c * L + l];
    }
    __syncthreads();
    size_t ob = (size_t)b * L * C;
#pragma unroll
    for (int j = 0; j < 32; j += 8) {
        int l = l0 + threadIdx.y + j, c = c0 + threadIdx.x;
        if (l < L && c < C) {
            float v = tile[threadIdx.x][threadIdx.y + j];
            if (xin) v = xin[ob + (size_t)l * C + c] - v;
            out[ob + (size_t)l * C + c] = v;
        }
    }
}

// CT permutation: xt2[row*16+l1][l2] = xt[row][l1 + 16*l2], pad l2=45..47 with 0
__global__ void make_xt2(const float* __restrict__ xt, float* __restrict__ xt2) {
    int row = blockIdx.x;
    int tid = threadIdx.x;
    const float* src = xt + (size_t)row * SEQL;
    float* dst = xt2 + (size_t)row * (L1F * K48);
    for (int i = tid; i < L1F * K48; i += 256) {
        int l1 = i / K48, l2 = i % K48;
        dst[i] = (l2 < L2F) ? src[l1 + L1F * l2] : 0.f;
    }
}

// ---------------- fp32 SGEMM: 128x128x8 tiles, 8x8 per thread ----------------
// Used for the selection-critical stage-1 spectrum GEMM (fp32 accuracy).
// Requirements: M % 128 == 0, K % 8 == 0, K >= 16, lda % 4 == 0. N guarded.
__global__ void __launch_bounds__(256) gemm128(
    const float* __restrict__ A, int lda,
    const float* __restrict__ B, int ldb,
    float* __restrict__ C, int ldc,
    int M, int N, int K) {
    __shared__ float As[8][132];
    __shared__ float Bs[8][128];
    const int tid = threadIdx.x;
    const int m0 = blockIdx.y * 128, n0 = blockIdx.x * 128;

    const int arow = tid >> 1, acol = (tid & 1) * 4;
    const int bk = tid >> 5, bn = (tid & 31) * 4;
    const int tn = (tid & 15) * 4;
    const int tm = (tid >> 4) * 4;

    float acc[2][4][2][4] = {};

    float4 aP = *reinterpret_cast<const float4*>(&A[(size_t)(m0 + arow) * lda + acol]);
    float bP0, bP1, bP2, bP3;
    {
        const float* Brow = &B[(size_t)bk * ldb];
        int n = n0 + bn;
        bP0 = (n + 0 < N) ? Brow[n + 0] : 0.f;
        bP1 = (n + 1 < N) ? Brow[n + 1] : 0.f;
        bP2 = (n + 2 < N) ? Brow[n + 2] : 0.f;
        bP3 = (n + 3 < N) ? Brow[n + 3] : 0.f;
    }

    for (int k0 = 0; k0 < K; k0 += 8) {
        As[acol + 0][arow] = aP.x;
        As[acol + 1][arow] = aP.y;
        As[acol + 2][arow] = aP.z;
        As[acol + 3][arow] = aP.w;
        *reinterpret_cast<float4*>(&Bs[bk][bn]) = make_float4(bP0, bP1, bP2, bP3);
        __syncthreads();

        if (k0 + 8 < K) {
            aP = *reinterpret_cast<const float4*>(&A[(size_t)(m0 + arow) * lda + (k0 + 8 + acol)]);
            const float* Brow = &B[(size_t)(k0 + 8 + bk) * ldb];
            int n = n0 + bn;
            bP0 = (n + 0 < N) ? Brow[n + 0] : 0.f;
            bP1 = (n + 1 < N) ? Brow[n + 1] : 0.f;
            bP2 = (n + 2 < N) ? Brow[n + 2] : 0.f;
            bP3 = (n + 3 < N) ? Brow[n + 3] : 0.f;
        }

#pragma unroll
        for (int kk = 0; kk < 8; kk++) {
            float af[8], bf[8];
            *reinterpret_cast<float4*>(&af[0]) = *reinterpret_cast<const float4*>(&As[kk][tm]);
            *reinterpret_cast<float4*>(&af[4]) = *reinterpret_cast<const float4*>(&As[kk][tm + 64]);
            *reinterpret_cast<float4*>(&bf[0]) = *reinterpret_cast<const float4*>(&Bs[kk][tn]);
            *reinterpret_cast<float4*>(&bf[4]) = *reinterpret_cast<const float4*>(&Bs[kk][tn + 64]);
#pragma unroll
            for (int mi = 0; mi < 2; mi++)
#pragma unroll
                for (int i = 0; i < 4; i++)
#pragma unroll
                    for (int ni = 0; ni < 2; ni++)
#pragma unroll
                        for (int j = 0; j < 4; j++)
                            acc[mi][i][ni][j] = fmaf(af[mi * 4 + i], bf[ni * 4 + j], acc[mi][i][ni][j]);
        }
        __syncthreads();
    }

#pragma unroll
    for (int mi = 0; mi < 2; mi++)
#pragma unroll
        for (int i = 0; i < 4; i++) {
            int gm = m0 + tm + mi * 64 + i;
#pragma unroll
            for (int ni = 0; ni < 2; ni++)
#pragma unroll
                for (int j = 0; j < 4; j++) {
                    int gn = n0 + tn + ni * 64 + j;
                    if (gn >= N) continue;
                    C[(size_t)gm * ldc + gn] = acc[mi][i][ni][j];
                }
        }
}

// ---------------- bf16 helpers ----------------
__device__ __forceinline__ void split_pack_bf16(float e, float o, uint32_t& hi, uint32_t& lo) {
    __nv_bfloat16 he = __float2bfloat16_rn(e);
    __nv_bfloat16 ho = __float2bfloat16_rn(o);
    float re = e - __bfloat162float(he);
    float ro = o - __bfloat162float(ho);
    __nv_bfloat16 le = __float2bfloat16_rn(re);
    __nv_bfloat16 lo2 = __float2bfloat16_rn(ro);
    unsigned short ue = *reinterpret_cast<unsigned short*>(&he);
    unsigned short uo = *reinterpret_cast<unsigned short*>(&ho);
    unsigned short ve = *reinterpret_cast<unsigned short*>(&le);
    unsigned short vo = *reinterpret_cast<unsigned short*>(&lo2);
    hi = ((uint32_t)uo << 16) | ue;
    lo = ((uint32_t)vo << 16) | ve;
}

__device__ __forceinline__ void mma_bf16(float* d, const uint32_t* a, const uint32_t* b) {
    asm volatile(
        "mma.sync.aligned.m16n8k16.row.col.f32.bf16.bf16.f32 "
        "{%0,%1,%2,%3}, {%4,%5,%6,%7}, {%8,%9}, {%0,%1,%2,%3};\n"
        : "+f"(d[0]), "+f"(d[1]), "+f"(d[2]), "+f"(d[3])
        : "r"(a[0]), "r"(a[1]), "r"(a[2]), "r"(a[3]), "r"(b[0]), "r"(b[1]));
}

// ------- tensor-core GEMM: 128M x 64N block, bf16 3-term split, m16n8k16 -------
// Requires M % 128 == 0, K % 16 == 0, lda % 4 == 0. N guarded.
// MODE 0: C = A@B + bias ; 1: relu ; 2: relu(+Cin) ; 3: Cin + relu
template <int MODE>
__global__ void __launch_bounds__(256) gemm_bf(
    const float* __restrict__ A, int lda,
    const float* __restrict__ B, int ldb,
    const float* __restrict__ bias,
    const float* __restrict__ Cin, int ldcin,
    float* __restrict__ C, int ldc,
    int M, int N, int K) {
    // packed k-pairs: [kp][m] / [kp][n], kp in [0,8) covers k in [0,16)
    __shared__ uint32_t Ah[8][136], Al[8][136];
    __shared__ uint32_t Bh[8][72],  Bl[8][72];

    const int tid = threadIdx.x;
    const int m0 = blockIdx.y * 128, n0 = blockIdx.x * 64;
    const int lane = tid & 31, warp = tid >> 5;
    const int wm = warp & 3, wn = warp >> 2;       // 4x2 warp grid
    const int m0w = wm * 32, n0w = wn * 32;        // 32x32 warp tile
    const int kq = lane & 3, gq = lane >> 2;

    const int arow = tid >> 1, ak = (tid & 1) * 8, akp = (tid & 1) * 4;
    const int bkp = tid >> 5, bn2 = (tid & 31) * 2;

    float acc[2][4][4];
#pragma unroll
    for (int i = 0; i < 2; i++)
#pragma unroll
        for (int j = 0; j < 4; j++)
#pragma unroll
            for (int q = 0; q < 4; q++) acc[i][j][q] = 0.f;

    // prefetch first tile
    float4 aP0 = *reinterpret_cast<const float4*>(&A[(size_t)(m0 + arow) * lda + ak]);
    float4 aP1 = *reinterpret_cast<const float4*>(&A[(size_t)(m0 + arow) * lda + ak + 4]);
    float be[2], bo[2];
    {
        const float* B0 = &B[(size_t)(2 * bkp) * ldb];
        const float* B1 = &B[(size_t)(2 * bkp + 1) * ldb];
#pragma unroll
        for (int i = 0; i < 2; i++) {
            int n = n0 + bn2 + i;
            be[i] = (n < N) ? B0[n] : 0.f;
            bo[i] = (n < N) ? B1[n] : 0.f;
        }
    }

    for (int k0 = 0; k0 < K; k0 += 16) {
        {
            float av[8] = {aP0.x, aP0.y, aP0.z, aP0.w, aP1.x, aP1.y, aP1.z, aP1.w};
#pragma unroll
            for (int i = 0; i < 4; i++) {
                uint32_t h, l;
                split_pack_bf16(av[2 * i], av[2 * i + 1], h, l);
                Ah[akp + i][arow] = h; Al[akp + i][arow] = l;
            }
#pragma unroll
            for (int i = 0; i < 2; i++) {
                uint32_t h, l;
                split_pack_bf16(be[i], bo[i], h, l);
                Bh[bkp][bn2 + i] = h; Bl[bkp][bn2 + i] = l;
            }
        }
        __syncthreads();

        if (k0 + 16 < K) {
            aP0 = *reinterpret_cast<const float4*>(&A[(size_t)(m0 + arow) * lda + (k0 + 16 + ak)]);
            aP1 = *reinterpret_cast<const float4*>(&A[(size_t)(m0 + arow) * lda + (k0 + 16 + ak + 4)]);
            const float* B0 = &B[(size_t)(k0 + 16 + 2 * bkp) * ldb];
            const float* B1 = &B[(size_t)(k0 + 16 + 2 * bkp + 1) * ldb];
#pragma unroll
            for (int i = 0; i < 2; i++) {
                int n = n0 + bn2 + i;
                be[i] = (n < N) ? B0[n] : 0.f;
                bo[i] = (n < N) ? B1[n] : 0.f;
            }
        }

        // one k16 MMA sweep
        uint32_t ah[2][4], al[2][4], bh[4][2], bl[4][2];
#pragma unroll
        for (int mi = 0; mi < 2; mi++) {
            int m = m0w + mi * 16 + gq;
            ah[mi][0] = Ah[kq][m];     ah[mi][1] = Ah[kq][m + 8];
            ah[mi][2] = Ah[kq + 4][m]; ah[mi][3] = Ah[kq + 4][m + 8];
            al[mi][0] = Al[kq][m];     al[mi][1] = Al[kq][m + 8];
            al[mi][2] = Al[kq + 4][m]; al[mi][3] = Al[kq + 4][m + 8];
        }
#pragma unroll
        for (int ni = 0; ni < 4; ni++) {
            int n = n0w + ni * 8 + gq;
            bh[ni][0] = Bh[kq][n]; bh[ni][1] = Bh[kq + 4][n];
            bl[ni][0] = Bl[kq][n]; bl[ni][1] = Bl[kq + 4][n];
        }
#pragma unroll
        for (int mi = 0; mi < 2; mi++)
#pragma unroll
            for (int ni = 0; ni < 4; ni++) {
                mma_bf16(acc[mi][ni], ah[mi], bh[ni]);
                mma_bf16(acc[mi][ni], al[mi], bh[ni]);
                mma_bf16(acc[mi][ni], ah[mi], bl[ni]);
            }
        __syncthreads();
    }

    // epilogue
#pragma unroll
    for (int mi = 0; mi < 2; mi++)
#pragma unroll
        for (int ni = 0; ni < 4; ni++)
#pragma unroll
            for (int hf = 0; hf < 2; hf++) {
                int gm = m0 + m0w + mi * 16 + gq + hf * 8;
                int gn = n0 + n0w + ni * 8 + kq * 2;
                float v0 = acc[mi][ni][hf * 2 + 0];
                float v1 = acc[mi][ni][hf * 2 + 1];
                bool ok0 = (gn < N), ok1 = (gn + 1 < N);
                if (bias) { if (ok0) v0 += bias[gn]; if (ok1) v1 += bias[gn + 1]; }
                if (MODE == 1) { v0 = fmaxf(v0, 0.f); v1 = fmaxf(v1, 0.f); }
                else if (MODE == 2) {
                    if (ok0) v0 += Cin[(size_t)gm * ldcin + gn];
                    if (ok1) v1 += Cin[(size_t)gm * ldcin + gn + 1];
                    v0 = fmaxf(v0, 0.f); v1 = fmaxf(v1, 0.f);
                } else if (MODE == 3) {
                    if (ok0) v0 = Cin[(size_t)gm * ldcin + gn] + fmaxf(v0, 0.f);
                    if (ok1) v1 = Cin[(size_t)gm * ldcin + gn + 1] + fmaxf(v1, 0.f);
                }
                if (ok0) C[(size_t)gm * ldc + gn]     = v0;
                if (ok1) C[(size_t)gm * ldc + gn + 1] = v1;
            }
}

// ------- stage-2 twiddle combine + per-row top-k + sparse irfft -------
__global__ void __launch_bounds__(256) topk2_reconstruct(
    const float* __restrict__ spec2, const int* __restrict__ kptr,
    const float* __restrict__ cosl, const float* __restrict__ sinl,
    float* __restrict__ filt) {
    int row = blockIdx.x;
    const float* srow = spec2 + (size_t)row * (L1F * N90);

    __shared__ float2 slut[SEQL];          // (cos, sin)
    __shared__ float sS[L1F][N90 + 2];     // stage-1 partials (padded)
    __shared__ float sXre[NFREQ], sXim[NFREQ], sMag[NFREQ];
    __shared__ int   sfreq[32];
    __shared__ float sre[32], sim[32];     // pre-scaled by weight/L
    __shared__ int   sk;

    int tid = threadIdx.x;
    for (int i = tid; i < SEQL; i += 256) slut[i] = make_float2(cosl[i], sinl[i]);
    for (int i = tid; i < L1F * N90; i += 256) {
        int l1 = i / N90, g = i % N90;
        sS[l1][g] = srow[i];
    }
    __syncthreads();

    // stage 2: X[f] = sum_{l1} S[l1][f%45] * e^{-2pi i f l1 / 720}
    for (int f = tid; f < NFREQ; f += 256) {
        int g = f % L2F;
        float xr = 0.f, xi = 0.f;
        int a = 0;
#pragma unroll
        for (int l1 = 0; l1 < L1F; l1++) {
            float2 w = slut[a];
            float sr = sS[l1][g];
            float si = sS[l1][L2F + g];
            xr = fmaf(sr, w.x, fmaf(si, w.y, xr));
            xi = fmaf(si, w.x, fmaf(-sr, w.y, xi));
            a += f; if (a >= SEQL) a -= SEQL;
        }
        sXre[f] = xr; sXim[f] = xi;
        sMag[f] = xr * xr + xi * xi;
    }
    __syncthreads();

    // warp-private top-k selection
    if (tid < 32) {
        int lane = tid;
        float mag[12];
#pragma unroll
        for (int j = 0; j < 12; j++) {
            int idx = lane + 32 * j;
            mag[j] = (idx < NFREQ) ? sMag[idx] : -1.f;
        }
        int k = *kptr;
        if (k > 32) k = 32;
        if (k < 0) k = 0;
        if (lane == 0) sk = k;
        const float scale = 1.f / (float)SEQL;
        for (int it = 0; it < k; it++) {
            float best = -1.f; int bslot = 0;
#pragma unroll
            for (int j = 0; j < 12; j++)
                if (mag[j] > best) { best = mag[j]; bslot = j; }
            int bidx = lane + 32 * bslot;
#pragma unroll
            for (int o = 16; o > 0; o >>= 1) {
                float ov = __shfl_xor_sync(0xffffffffu, best, o);
                int   oi = __shfl_xor_sync(0xffffffffu, bidx, o);
                if (ov > best || (ov == best && oi < bidx)) { best = ov; bidx = oi; }
            }
            if ((bidx & 31) == lane) {
                int j = bidx >> 5;
                float w = (bidx == 0 || bidx == NFREQ - 1) ? scale : 2.f * scale;
                sfreq[it] = bidx;
                sre[it] = sXre[bidx] * w;
                sim[it] = sXim[bidx] * w;
                mag[j] = -2.f;
            }
        }
    }
    __syncthreads();

    int k = sk;
    float* outp = filt + (size_t)row * SEQL;
    if (tid < 240) {
        int t0 = 3 * tid;
        float acc0 = 0.f, acc1 = 0.f, acc2 = 0.f;
        for (int j = 0; j < k; j++) {
            int f = sfreq[j];
            float r = sre[j], m = sim[j];
            int a0 = (f * t0) % SEQL;
            int a1 = a0 + f; if (a1 >= SEQL) a1 -= SEQL;
            int a2 = a1 + f; if (a2 >= SEQL) a2 -= SEQL;
            float2 p0 = slut[a0], p1 = slut[a1], p2 = slut[a2];
            acc0 = fmaf(r, p0.x, fmaf(-m, p0.y, acc0));
            acc1 = fmaf(r, p1.x, fmaf(-m, p1.y, acc1));
            acc2 = fmaf(r, p2.x, fmaf(-m, p2.y, acc2));
        }
        outp[t0 + 0] = acc0;
        outp[t0 + 1] = acc1;
        outp[t0 + 2] = acc2;
    }
}

// ---------------- host launch ----------------
extern "C" void kernel_launch(void* const* d_in, const int* in_sizes, int n_in,
                              void* d_out, int out_size) {
    const float* x      = (const float*)d_in[0];
    const float* w_freq = (const float*)d_in[1];
    const float* b_freq = (const float*)d_in[2];
    const float* w_all1 = (const float*)d_in[3];
    const float* b_all1 = (const float*)d_in[4];
    const float* w_all2 = (const float*)d_in[5];
    const float* b_all2 = (const float*)d_in[6];
    const float* w_time = (const float*)d_in[7];
    const float* b_time = (const float*)d_in[8];
    const float* w_chan = (const float*)d_in[9];
    const float* b_chan = (const float*)d_in[10];
    const float* w_proj = (const float*)d_in[11];
    const float* b_proj = (const float*)d_in[12];
    const int*   kptr   = (const int*)d_in[13];
    float* out = (float*)d_out;
    size_t half = (size_t)out_size / 2;

    float *basis45, *cosl, *sinl, *xt, *xt2, *spec2, *filt, *h, *z1, *z, *t, *tT, *cm, *cT, *pred;
    cudaGetSymbolAddress((void**)&basis45, g_basis45);
    cudaGetSymbolAddress((void**)&cosl, g_cosl);
    cudaGetSymbolAddress((void**)&sinl, g_sinl);
    cudaGetSymbolAddress((void**)&xt, g_xt);
    cudaGetSymbolAddress((void**)&xt2, g_xt2);
    cudaGetSymbolAddress((void**)&spec2, g_spec2);
    cudaGetSymbolAddress((void**)&filt, g_filt);
    cudaGetSymbolAddress((void**)&h, g_h);
    cudaGetSymbolAddress((void**)&z1, g_z1);
    cudaGetSymbolAddress((void**)&z, g_z);
    cudaGetSymbolAddress((void**)&t, g_t);
    cudaGetSymbolAddress((void**)&tT, g_tT);
    cudaGetSymbolAddress((void**)&cm, g_cm);
    cudaGetSymbolAddress((void**)&cT, g_cT);
    cudaGetSymbolAddress((void**)&pred, g_pred);

    dim3 tb(32, 8);

    // 0) twiddle LUTs + DFT45 basis
    fill_luts<<<(K48 * N90 + 255) / 256, 256>>>(basis45, cosl, sinl);

    // 1) x (b,L,C) -> xt (b,C,L)
    transpose_batched<<<dim3(ENC / 32, (SEQL + 31) / 32, BATCH), tb>>>(x, xt, SEQL, ENC);

    // 2) CT permute: xt -> xt2
    make_xt2<<<NROWS, 256>>>(xt, xt2);

    // 3) stage-1 spectra: spec2 = xt2 @ basis45  (fp32: selection-critical)
    gemm128<<<dim3(1, (NROWS * L1F) / 128), 256>>>(
        xt2, K48, basis45, N90, spec2, N90, NROWS * L1F, N90, K48);

    // 4) stage-2 combine + top-k + sparse irfft -> filt
    topk2_reconstruct<<<NROWS, 256>>>(spec2, kptr, cosl, sinl, filt);

    // 5) residual = x - filt^T  -> first half of d_out
    transpose_sub<<<dim3((SEQL + 31) / 32, ENC / 32, BATCH), tb>>>(filt, x, out, SEQL, ENC);

    // 6) h = relu(filt @ w_freq + b_freq)   (N=64, K=720)
    gemm_bf<1><<<dim3(1, NROWS / 128), 256>>>(
        filt, SEQL, w_freq, H_FREQ, b_freq, nullptr, 0, h, H_FREQ, NROWS, H_FREQ, SEQL);

    // 7) z1 = h @ w_all1[0:64] + b_all1 ; then z1 = relu(xt @ w_all1[64:] + z1)
    gemm_bf<0><<<dim3(H1 / 64, NROWS / 128), 256>>>(
        h, H_FREQ, w_all1, H1, b_all1, nullptr, 0, z1, H1, NROWS, H1, H_FREQ);
    gemm_bf<2><<<dim3(H1 / 64, NROWS / 128), 256>>>(
        xt, SEQL, w_all1 + (size_t)H_FREQ * H1, H1, nullptr, z1, H1, z1, H1, NROWS, H1, SEQL);

    // 8) z = z1 @ w_all2 + b_all2
    gemm_bf<0><<<dim3(H2 / 64, NROWS / 128), 256>>>(
        z1, H1, w_all2, H2, b_all2, nullptr, 0, z, H2, NROWS, H2, H1);

    // 9) t = z + relu(z @ w_time + b_time)
    gemm_bf<3><<<dim3(H2 / 64, NROWS / 128), 256>>>(
        z, H2, w_time, H2, b_time, z, H2, t, H2, NROWS, H2, H2);

    // 10) t (b,C,H2) -> tT (b,H2,C)
    transpose_batched<<<dim3(H2 / 32, ENC / 32, BATCH), tb>>>(t, tT, ENC, H2);

    // 11) cm = tT + relu(tT @ w_chan + b_chan)   (rows = b*H2 = 16384, N=K=512)
    gemm_bf<3><<<dim3(ENC / 64, (BATCH * H2) / 128), 256>>>(
        tT, ENC, w_chan, ENC, b_chan, tT, ENC, cm, ENC, BATCH * H2, ENC, ENC);

    // 12) cm (b,H2,C) -> cT (b,C,H2)
    transpose_batched<<<dim3(ENC / 32, H2 / 32, BATCH), tb>>>(cm, cT, H2, ENC);

    // 13) pred = cT @ w_proj + b_proj   (32768 x 720, K=256)
    gemm_bf<0><<<dim3((PREDL + 63) / 64, NROWS / 128), 256>>>(
        cT, H2, w_proj, PREDL, b_proj, nullptr, 0, pred, PREDL, NROWS, PREDL, H2);

    // 14) pred (b,c,l) -> (b,l,c) into second half of d_out
    transpose_sub<<<dim3((PREDL + 31) / 32, ENC / 32, BATCH), tb>>>(
        pred, nullptr, out + half, PREDL, ENC);
}

// round 11
// speedup vs baseline: 2.5721x; 1.2325x over previous
#include <cuda_runtime.h>
#include <cuda_bf16.h>
#include <cstdint>
#include <cstddef>

// ---------------- problem constants ----------------
#define BATCH   64
#define SEQL    720      // L = 16 * 45
#define ENC     512      // C
#define NROWS   (BATCH*ENC)       // 32768
#define NFREQ   361               // rfft bins
#define H_FREQ  64
#define H1      128
#define H2      256
#define PREDL   720

#define L1F     16       // first CT factor
#define L2F     45       // second CT factor
#define NB      48       // stage-1 output width: [cos 0..22 | pad | -sin 0..22 | pad]

// ---------------- scratch (device globals; no allocs allowed) ----------------
__device__ float g_basis45[L2F*NB];           // DFT45 half-spectrum basis
__device__ float g_cosl[SEQL];
__device__ float g_sinl[SEQL];
__device__ float g_xt  [(size_t)NROWS*SEQL];  // x channel-major (b,c,l)
__device__ float g_spec2[(size_t)NROWS*L1F*NB]; // stage-1 partial half-spectra
__device__ float g_filt[(size_t)NROWS*SEQL];
__device__ float g_h   [(size_t)NROWS*H_FREQ];
__device__ float g_z1  [(size_t)NROWS*H1];
__device__ float g_z   [(size_t)NROWS*H2];
__device__ float g_t   [(size_t)NROWS*H2];
__device__ float g_tT  [(size_t)BATCH*H2*ENC];
__device__ float g_cm  [(size_t)BATCH*H2*ENC];
__device__ float g_cT  [(size_t)NROWS*H2];
__device__ float g_pred[(size_t)NROWS*PREDL];

// ---------------- LUT / basis fill ----------------
__global__ void fill_luts(float* __restrict__ basis45, float* __restrict__ cosl,
                          float* __restrict__ sinl) {
    int idx = blockIdx.x * blockDim.x + threadIdx.x;
    if (idx < SEQL) {
        double s, c;
        sincospi((double)(2 * idx) / (double)SEQL, &s, &c);
        cosl[idx] = (float)c;
        sinl[idx] = (float)s;
    }
    if (idx < L2F * NB) {
        int l2 = idx / NB, c = idx % NB;
        float v = 0.f;
        if (c < 23 || (c >= 24 && c < 47)) {
            int g = (c < 23) ? c : (c - 24);
            int a = (g * l2) % L2F;
            double s, cc;
            sincospi((double)(2 * a) / (double)L2F, &s, &cc);
            v = (c < 23) ? (float)cc : (float)(-s);
        }
        basis45[idx] = v;
    }
}

// ---------------- batched transpose (B,R,C) -> (B,C,R) ----------------
__global__ void transpose_batched(const float* __restrict__ in, float* __restrict__ out,
                                  int R, int C) {
    __shared__ float tile[32][33];
    int b = blockIdx.z;
    int c0 = blockIdx.x * 32, r0 = blockIdx.y * 32;
    const float* pin = in + (size_t)b * R * C;
    float* pout = out + (size_t)b * R * C;
    int tx = threadIdx.x, ty = threadIdx.y;
#pragma unroll
    for (int j = 0; j < 32; j += 8) {
        int r = r0 + ty + j, c = c0 + tx;
        if (r < R && c < C) tile[ty + j][tx] = pin[(size_t)r * C + c];
    }
    __syncthreads();
#pragma unroll
    for (int j = 0; j < 32; j += 8) {
        int c = c0 + ty + j, r = r0 + tx;
        if (c < C && r < R) pout[(size_t)c * R + r] = tile[tx][ty + j];
    }
}

// src: (B,C,L) channel-major; out: (B,L,C); if xin != null, out = xin - src^T
__global__ void transpose_sub(const float* __restrict__ src, const float* __restrict__ xin,
                              float* __restrict__ out, int L, int C) {
    __shared__ float tile[32][33];
    int b = blockIdx.z;
    int l0 = blockIdx.x * 32, c0 = blockIdx.y * 32;
    const float* ps = src + (size_t)b * C * L;
#pragma unroll
    for (int j = 0; j < 32; j += 8) {
        int c = c0 + threadIdx.y + j, l = l0 + threadIdx.x;
        if (c < C && l < L) tile[threadIdx.y + j][threadIdx.x] = ps[(size_t)c * L + l];
    }
    __syncthreads();
    size_t ob = (size_t)b * L * C;
#pragma unroll
    for (int j = 0; j < 32; j += 8) {
        int l = l0 + threadIdx.y + j, c = c0 + threadIdx.x;
        if (l < L && c < C) {
            float v = tile[threadIdx.x][threadIdx.y + j];
            if (xin) v = xin[ob + (size_t)l * C + c] - v;
            out[ob + (size_t)l * C + c] = v;
        }
    }
}

// ------- stage-1: per-block 8 xt rows x full DFT45 half-spectrum (fp32) -------
// spec2[(row*16+l1)*48 + c] = sum_{l2<45} xt[row][l1+16*l2] * basis45[l2][c]
// CT permutation folded into the smem A read. Sequential l2 accumulation
// (bitwise-matches the previous gemm128 k-order for direct bins).
__global__ void __launch_bounds__(256) gemm_s1(
    const float* __restrict__ xt, const float* __restrict__ basis,
    float* __restrict__ spec2) {
    __shared__ float Axt[8][SEQL];
    __shared__ float Bs[L2F][NB];
    const int tid = threadIdx.x;
    const size_t base = (size_t)blockIdx.x * (8 * SEQL);

    {
        const float4* src = reinterpret_cast<const float4*>(xt + base);
        float4* dst = reinterpret_cast<float4*>(&Axt[0][0]);
        for (int i = tid; i < 8 * SEQL / 4; i += 256) dst[i] = src[i];
    }
    {
        const float4* src = reinterpret_cast<const float4*>(basis);
        float4* dst = reinterpret_cast<float4*>(&Bs[0][0]);
        for (int i = tid; i < L2F * NB / 4; i += 256) dst[i] = src[i];
    }
    __syncthreads();

    const int tm = (tid >> 3) * 4;   // CT-row base 0..124
    const int tn = (tid & 7) * 6;    // col base 0..42
    const int orig = tm >> 4;        // original row within block (0..7)
    const int l1b = tm & 15;         // l1 base (0,4,8,12)

    float acc[4][6] = {};
#pragma unroll 15
    for (int k = 0; k < L2F; k++) {
        float4 av = *reinterpret_cast<const float4*>(&Axt[orig][l1b + 16 * k]);
        float2 b0 = *reinterpret_cast<const float2*>(&Bs[k][tn]);
        float2 b1 = *reinterpret_cast<const float2*>(&Bs[k][tn + 2]);
        float2 b2 = *reinterpret_cast<const float2*>(&Bs[k][tn + 4]);
        float a[4] = {av.x, av.y, av.z, av.w};
        float b[6] = {b0.x, b0.y, b1.x, b1.y, b2.x, b2.y};
#pragma unroll
        for (int i = 0; i < 4; i++)
#pragma unroll
            for (int j = 0; j < 6; j++)
                acc[i][j] = fmaf(a[i], b[j], acc[i][j]);
    }

    size_t gmbase = (size_t)blockIdx.x * 128 + tm;
#pragma unroll
    for (int i = 0; i < 4; i++) {
        float* orow = spec2 + (gmbase + i) * NB + tn;
#pragma unroll
        for (int j = 0; j < 6; j += 2)
            *reinterpret_cast<float2*>(&orow[j]) = make_float2(acc[i][j], acc[i][j + 1]);
    }
}

// ---------------- bf16 helpers ----------------
__device__ __forceinline__ void split_pack_bf16(float e, float o, uint32_t& hi, uint32_t& lo) {
    __nv_bfloat16 he = __float2bfloat16_rn(e);
    __nv_bfloat16 ho = __float2bfloat16_rn(o);
    float re = e - __bfloat162float(he);
    float ro = o - __bfloat162float(ho);
    __nv_bfloat16 le = __float2bfloat16_rn(re);
    __nv_bfloat16 lo2 = __float2bfloat16_rn(ro);
    unsigned short ue = *reinterpret_cast<unsigned short*>(&he);
    unsigned short uo = *reinterpret_cast<unsigned short*>(&ho);
    unsigned short ve = *reinterpret_cast<unsigned short*>(&le);
    unsigned short vo = *reinterpret_cast<unsigned short*>(&lo2);
    hi = ((uint32_t)uo << 16) | ue;
    lo = ((uint32_t)vo << 16) | ve;
}

__device__ __forceinline__ void mma_bf16(float* d, const uint32_t* a, const uint32_t* b) {
    asm volatile(
        "mma.sync.aligned.m16n8k16.row.col.f32.bf16.bf16.f32 "
        "{%0,%1,%2,%3}, {%4,%5,%6,%7}, {%8,%9}, {%0,%1,%2,%3};\n"
        : "+f"(d[0]), "+f"(d[1]), "+f"(d[2]), "+f"(d[3])
        : "r"(a[0]), "r"(a[1]), "r"(a[2]), "r"(a[3]), "r"(b[0]), "r"(b[1]));
}

// ------- tensor-core GEMM: 128M x 64N block, bf16 3-term split, m16n8k16 -------
// hi/lo interleaved as uint2 -> LDS.64 fragment loads. Rows padded (140/76)
// so the 4 kq row-offsets land in distinct bank groups.
// Requires M % 128 == 0, K % 16 == 0, lda % 4 == 0. N guarded.
// MODE 0: C = A@B + bias ; 1: relu ; 2: relu(+Cin) ; 3: Cin + relu
template <int MODE>
__global__ void __launch_bounds__(256) gemm_bf(
    const float* __restrict__ A, int lda,
    const float* __restrict__ B, int ldb,
    const float* __restrict__ bias,
    const float* __restrict__ Cin, int ldcin,
    float* __restrict__ C, int ldc,
    int M, int N, int K) {
    __shared__ uint2 As[8][140];   // [kp][m] (hi, lo)
    __shared__ uint2 Bs[8][76];    // [kp][n]

    const int tid = threadIdx.x;
    const int m0 = blockIdx.y * 128, n0 = blockIdx.x * 64;
    const int lane = tid & 31, warp = tid >> 5;
    const int wm = warp & 3, wn = warp >> 2;       // 4x2 warp grid
    const int m0w = wm * 32, n0w = wn * 32;        // 32x32 warp tile
    const int kq = lane & 3, gq = lane >> 2;

    const int arow = tid >> 1, ak = (tid & 1) * 8, akp = (tid & 1) * 4;
    const int bkp = tid >> 5, bn2 = (tid & 31) * 2;

    float acc[2][4][4];
#pragma unroll
    for (int i = 0; i < 2; i++)
#pragma unroll
        for (int j = 0; j < 4; j++)
#pragma unroll
            for (int q = 0; q < 4; q++) acc[i][j][q] = 0.f;

    // prefetch first tile
    float4 aP0 = *reinterpret_cast<const float4*>(&A[(size_t)(m0 + arow) * lda + ak]);
    float4 aP1 = *reinterpret_cast<const float4*>(&A[(size_t)(m0 + arow) * lda + ak + 4]);
    float be[2], bo[2];
    {
        const float* B0 = &B[(size_t)(2 * bkp) * ldb];
        const float* B1 = &B[(size_t)(2 * bkp + 1) * ldb];
#pragma unroll
        for (int i = 0; i < 2; i++) {
            int n = n0 + bn2 + i;
            be[i] = (n < N) ? B0[n] : 0.f;
            bo[i] = (n < N) ? B1[n] : 0.f;
        }
    }

    for (int k0 = 0; k0 < K; k0 += 16) {
        {
            float av[8] = {aP0.x, aP0.y, aP0.z, aP0.w, aP1.x, aP1.y, aP1.z, aP1.w};
#pragma unroll
            for (int i = 0; i < 4; i++) {
                uint32_t h, l;
                split_pack_bf16(av[2 * i], av[2 * i + 1], h, l);
                As[akp + i][arow] = make_uint2(h, l);
            }
#pragma unroll
            for (int i = 0; i < 2; i++) {
                uint32_t h, l;
                split_pack_bf16(be[i], bo[i], h, l);
                Bs[bkp][bn2 + i] = make_uint2(h, l);
            }
        }
        __syncthreads();

        if (k0 + 16 < K) {
            aP0 = *reinterpret_cast<const float4*>(&A[(size_t)(m0 + arow) * lda + (k0 + 16 + ak)]);
            aP1 = *reinterpret_cast<const float4*>(&A[(size_t)(m0 + arow) * lda + (k0 + 16 + ak + 4)]);
            const float* B0 = &B[(size_t)(k0 + 16 + 2 * bkp) * ldb];
            const float* B1 = &B[(size_t)(k0 + 16 + 2 * bkp + 1) * ldb];
#pragma unroll
            for (int i = 0; i < 2; i++) {
                int n = n0 + bn2 + i;
                be[i] = (n < N) ? B0[n] : 0.f;
                bo[i] = (n < N) ? B1[n] : 0.f;
            }
        }

        // one k16 MMA sweep
        uint32_t ah[2][4], al[2][4], bh[4][2], bl[4][2];
#pragma unroll
        for (int mi = 0; mi < 2; mi++) {
            int m = m0w + mi * 16 + gq;
            uint2 a00 = As[kq][m],     a01 = As[kq][m + 8];
            uint2 a10 = As[kq + 4][m], a11 = As[kq + 4][m + 8];
            ah[mi][0] = a00.x; ah[mi][1] = a01.x; ah[mi][2] = a10.x; ah[mi][3] = a11.x;
            al[mi][0] = a00.y; al[mi][1] = a01.y; al[mi][2] = a10.y; al[mi][3] = a11.y;
        }
#pragma unroll
        for (int ni = 0; ni < 4; ni++) {
            int n = n0w + ni * 8 + gq;
            uint2 b0 = Bs[kq][n], b1 = Bs[kq + 4][n];
            bh[ni][0] = b0.x; bh[ni][1] = b1.x;
            bl[ni][0] = b0.y; bl[ni][1] = b1.y;
        }
#pragma unroll
        for (int mi = 0; mi < 2; mi++)
#pragma unroll
            for (int ni = 0; ni < 4; ni++) {
                mma_bf16(acc[mi][ni], ah[mi], bh[ni]);
                mma_bf16(acc[mi][ni], al[mi], bh[ni]);
                mma_bf16(acc[mi][ni], ah[mi], bl[ni]);
            }
        __syncthreads();
    }

    // epilogue
#pragma unroll
    for (int mi = 0; mi < 2; mi++)
#pragma unroll
        for (int ni = 0; ni < 4; ni++)
#pragma unroll
            for (int hf = 0; hf < 2; hf++) {
                int gm = m0 + m0w + mi * 16 + gq + hf * 8;
                int gn = n0 + n0w + ni * 8 + kq * 2;
                float v0 = acc[mi][ni][hf * 2 + 0];
                float v1 = acc[mi][ni][hf * 2 + 1];
                bool ok0 = (gn < N), ok1 = (gn + 1 < N);
                if (bias) { if (ok0) v0 += bias[gn]; if (ok1) v1 += bias[gn + 1]; }
                if (MODE == 1) { v0 = fmaxf(v0, 0.f); v1 = fmaxf(v1, 0.f); }
                else if (MODE == 2) {
                    if (ok0) v0 += Cin[(size_t)gm * ldcin + gn];
                    if (ok1) v1 += Cin[(size_t)gm * ldcin + gn + 1];
                    v0 = fmaxf(v0, 0.f); v1 = fmaxf(v1, 0.f);
                } else if (MODE == 3) {
                    if (ok0) v0 = Cin[(size_t)gm * ldcin + gn] + fmaxf(v0, 0.f);
                    if (ok1) v1 = Cin[(size_t)gm * ldcin + gn + 1] + fmaxf(v1, 0.f);
                }
                if (ok0) C[(size_t)gm * ldc + gn]     = v0;
                if (ok1) C[(size_t)gm * ldc + gn + 1] = v1;
            }
}

// ------- stage-2 twiddle combine + per-row top-k + rotation irfft -------
__global__ void __launch_bounds__(256) topk2_reconstruct(
    const float* __restrict__ spec2, const int* __restrict__ kptr,
    const float* __restrict__ cosl, const float* __restrict__ sinl,
    float* __restrict__ filt) {
    int row = blockIdx.x;
    const float* srow = spec2 + (size_t)row * (L1F * NB);

    __shared__ float2 slut[SEQL];          // (cos, sin)
    __shared__ float sS[L1F][NB];          // stage-1 half-spectra
    __shared__ float sXre[NFREQ], sXim[NFREQ], sMag[NFREQ];
    __shared__ int    sfreq[32];
    __shared__ float  sre[32], sim[32];    // pre-scaled by weight/L
    __shared__ float2 swt[32];             // per-freq rotation twiddle
    __shared__ int    sk;

    int tid = threadIdx.x;
    for (int i = tid; i < SEQL; i += 256) slut[i] = make_float2(cosl[i], sinl[i]);
    for (int i = tid; i < L1F * NB; i += 256) (&sS[0][0])[i] = srow[i];
    __syncthreads();

    // stage 2: X[f] = sum_{l1} S[l1][f%45] * e^{-2pi i f l1 / 720}
    // mirror bins via conjugate symmetry of the real DFT45.
    for (int f = tid; f < NFREQ; f += 256) {
        int g = f % L2F;
        int gc = g; float sgn = 1.f;
        if (g >= 23) { gc = L2F - g; sgn = -1.f; }
        float xr = 0.f, xi = 0.f;
        int a = 0;
#pragma unroll
        for (int l1 = 0; l1 < L1F; l1++) {
            float2 w = slut[a];
            float sr = sS[l1][gc];
            float si = sgn * sS[l1][24 + gc];
            xr = fmaf(sr, w.x, fmaf(si, w.y, xr));
            xi = fmaf(si, w.x, fmaf(-sr, w.y, xi));
            a += f; if (a >= SEQL) a -= SEQL;
        }
        sXre[f] = xr; sXim[f] = xi;
        sMag[f] = xr * xr + xi * xi;
    }
    __syncthreads();

    // warp-private top-k selection
    if (tid < 32) {
        int lane = tid;
        float mag[12];
#pragma unroll
        for (int j = 0; j < 12; j++) {
            int idx = lane + 32 * j;
            mag[j] = (idx < NFREQ) ? sMag[idx] : -1.f;
        }
        int k = *kptr;
        if (k > 32) k = 32;
        if (k < 0) k = 0;
        if (lane == 0) sk = k;
        const float scale = 1.f / (float)SEQL;
        for (int it = 0; it < k; it++) {
            float best = -1.f; int bslot = 0;
#pragma unroll
            for (int j = 0; j < 12; j++)
                if (mag[j] > best) { best = mag[j]; bslot = j; }
            int bidx = lane + 32 * bslot;
#pragma unroll
            for (int o = 16; o > 0; o >>= 1) {
                float ov = __shfl_xor_sync(0xffffffffu, best, o);
                int   oi = __shfl_xor_sync(0xffffffffu, bidx, o);
                if (ov > best || (ov == best && oi < bidx)) { best = ov; bidx = oi; }
            }
            if ((bidx & 31) == lane) {
                int j = bidx >> 5;
                float w = (bidx == 0 || bidx == NFREQ - 1) ? scale : 2.f * scale;
                sfreq[it] = bidx;
                sre[it] = sXre[bidx] * w;
                sim[it] = sXim[bidx] * w;
                swt[it] = slut[bidx];
                mag[j] = -2.f;
            }
        }
    }
    __syncthreads();

    int k = sk;
    float* outp = filt + (size_t)row * SEQL;
    if (tid < 240) {
        int t0 = 3 * tid;
        float acc0 = 0.f, acc1 = 0.f, acc2 = 0.f;
        for (int j = 0; j < k; j++) {
            int f = sfreq[j];
            float r = sre[j], m = sim[j];
            float2 w = swt[j];
            int a0 = (f * t0) % SEQL;
            float2 p0 = slut[a0];
            acc0 = fmaf(r, p0.x, fmaf(-m, p0.y, acc0));
            float2 p1;
            p1.x = fmaf(-p0.y, w.y, p0.x * w.x);
            p1.y = fmaf(p0.x, w.y, p0.y * w.x);
            acc1 = fmaf(r, p1.x, fmaf(-m, p1.y, acc1));
            float2 p2;
            p2.x = fmaf(-p1.y, w.y, p1.x * w.x);
            p2.y = fmaf(p1.x, w.y, p1.y * w.x);
            acc2 = fmaf(r, p2.x, fmaf(-m, p2.y, acc2));
        }
        outp[t0 + 0] = acc0;
        outp[t0 + 1] = acc1;
        outp[t0 + 2] = acc2;
    }
}

// ---------------- host launch ----------------
extern "C" void kernel_launch(void* const* d_in, const int* in_sizes, int n_in,
                              void* d_out, int out_size) {
    const float* x      = (const float*)d_in[0];
    const float* w_freq = (const float*)d_in[1];
    const float* b_freq = (const float*)d_in[2];
    const float* w_all1 = (const float*)d_in[3];
    const float* b_all1 = (const float*)d_in[4];
    const float* w_all2 = (const float*)d_in[5];
    const float* b_all2 = (const float*)d_in[6];
    const float* w_time = (const float*)d_in[7];
    const float* b_time = (const float*)d_in[8];
    const float* w_chan = (const float*)d_in[9];
    const float* b_chan = (const float*)d_in[10];
    const float* w_proj = (const float*)d_in[11];
    const float* b_proj = (const float*)d_in[12];
    const int*   kptr   = (const int*)d_in[13];
    float* out = (float*)d_out;
    size_t half = (size_t)out_size / 2;

    float *basis45, *cosl, *sinl, *xt, *spec2, *filt, *h, *z1, *z, *t, *tT, *cm, *cT, *pred;
    cudaGetSymbolAddress((void**)&basis45, g_basis45);
    cudaGetSymbolAddress((void**)&cosl, g_cosl);
    cudaGetSymbolAddress((void**)&sinl, g_sinl);
    cudaGetSymbolAddress((void**)&xt, g_xt);
    cudaGetSymbolAddress((void**)&spec2, g_spec2);
    cudaGetSymbolAddress((void**)&filt, g_filt);
    cudaGetSymbolAddress((void**)&h, g_h);
    cudaGetSymbolAddress((void**)&z1, g_z1);
    cudaGetSymbolAddress((void**)&z, g_z);
    cudaGetSymbolAddress((void**)&t, g_t);
    cudaGetSymbolAddress((void**)&tT, g_tT);
    cudaGetSymbolAddress((void**)&cm, g_cm);
    cudaGetSymbolAddress((void**)&cT, g_cT);
    cudaGetSymbolAddress((void**)&pred, g_pred);

    dim3 tb(32, 8);

    // 0) twiddle LUTs + DFT45 half-spectrum basis
    fill_luts<<<(L2F * NB + 255) / 256, 256>>>(basis45, cosl, sinl);

    // 1) x (b,L,C) -> xt (b,C,L)
    transpose_batched<<<dim3(ENC / 32, (SEQL + 31) / 32, BATCH), tb>>>(x, xt, SEQL, ENC);

    // 2) stage-1 half-spectra (fp32, fused CT permutation)
    gemm_s1<<<NROWS / 8, 256>>>(xt, basis45, spec2);

    // 3) stage-2 combine + top-k + rotation irfft -> filt
    topk2_reconstruct<<<NROWS, 256>>>(spec2, kptr, cosl, sinl, filt);

    // 4) residual = x - filt^T  -> first half of d_out
    transpose_sub<<<dim3((SEQL + 31) / 32, ENC / 32, BATCH), tb>>>(filt, x, out, SEQL, ENC);

    // 5) h = relu(filt @ w_freq + b_freq)   (N=64, K=720)
    gemm_bf<1><<<dim3(1, NROWS / 128), 256>>>(
        filt, SEQL, w_freq, H_FREQ, b_freq, nullptr, 0, h, H_FREQ, NROWS, H_FREQ, SEQL);

    // 6) z1 = h @ w_all1[0:64] + b_all1 ; then z1 = relu(xt @ w_all1[64:] + z1)
    gemm_bf<0><<<dim3(H1 / 64, NROWS / 128), 256>>>(
        h, H_FREQ, w_all1, H1, b_all1, nullptr, 0, z1, H1, NROWS, H1, H_FREQ);
    gemm_bf<2><<<dim3(H1 / 64, NROWS / 128), 256>>>(
        xt, SEQL, w_all1 + (size_t)H_FREQ * H1, H1, nullptr, z1, H1, z1, H1, NROWS, H1, SEQL);

    // 7) z = z1 @ w_all2 + b_all2
    gemm_bf<0><<<dim3(H2 / 64, NROWS / 128), 256>>>(
        z1, H1, w_all2, H2, b_all2, nullptr, 0, z, H2, NROWS, H2, H1);

    // 8) t = z + relu(z @ w_time + b_time)
    gemm_bf<3><<<dim3(H2 / 64, NROWS / 128), 256>>>(
        z, H2, w_time, H2, b_time, z, H2, t, H2, NROWS, H2, H2);

    // 9) t (b,C,H2) -> tT (b,H2,C)
    transpose_batched<<<dim3(H2 / 32, ENC / 32, BATCH), tb>>>(t, tT, ENC, H2);

    // 10) cm = tT + relu(tT @ w_chan + b_chan)   (rows = b*H2 = 16384, N=K=512)
    gemm_bf<3><<<dim3(ENC / 64, (BATCH * H2) / 128), 256>>>(
        tT, ENC, w_chan, ENC, b_chan, tT, ENC, cm, ENC, BATCH * H2, ENC, ENC);

    // 11) cm (b,H2,C) -> cT (b,C,H2)
    transpose_batched<<<dim3(ENC / 32, H2 / 32, BATCH), tb>>>(cm, cT, H2, ENC);

    // 12) pred = cT @ w_proj + b_proj   (32768 x 720, K=256)
    gemm_bf<0><<<dim3((PREDL + 63) / 64, NROWS / 128), 256>>>(
        cT, H2, w_proj, PREDL, b_proj, nullptr, 0, pred, PREDL, NROWS, PREDL, H2);

    // 13) pred (b,c,l) -> (b,l,c) into second half of d_out
    transpose_sub<<<dim3((PREDL + 31) / 32, ENC / 32, BATCH), tb>>>(
        pred, nullptr, out + half, PREDL, ENC);
}

// round 12
// speedup vs baseline: 2.7665x; 1.0756x over previous
#include <cuda_runtime.h>
#include <cuda_bf16.h>
#include <cstdint>
#include <cstddef>

// ---------------- problem constants ----------------
#define BATCH   64
#define SEQL    720      // L = 16 * 45
#define ENC     512      // C
#define NROWS   (BATCH*ENC)       // 32768
#define NFREQ   361               // rfft bins
#define H_FREQ  64
#define H1      128
#define H2      256
#define PREDL   720

#define L1F     16       // first CT factor
#define L2F     45       // second CT factor
#define NB      48       // stage-1 output width: [cos 0..22 | pad | -sin 0..22 | pad]

// ---------------- scratch (device globals; no allocs allowed) ----------------
__device__ float g_basis45[L2F*NB];           // DFT45 half-spectrum basis
__device__ float g_cosl[SEQL];
__device__ float g_sinl[SEQL];
__device__ float g_xt  [(size_t)NROWS*SEQL];  // x channel-major (b,c,l)
__device__ float g_spec2[(size_t)NROWS*L1F*NB]; // stage-1 partial half-spectra
__device__ float4 g_coef4[(size_t)NROWS*32];  // (re*w, im*w, twid.x, twid.y)
__device__ int    g_coefI[(size_t)NROWS*32];  // selected freq
__device__ float g_filt[(size_t)NROWS*SEQL];
__device__ float g_h   [(size_t)NROWS*H_FREQ];
__device__ float g_z1  [(size_t)NROWS*H1];
__device__ float g_z   [(size_t)NROWS*H2];
__device__ float g_t   [(size_t)NROWS*H2];
__device__ float g_wchT[(size_t)ENC*ENC];     // w_chan transposed
__device__ float g_cT  [(size_t)NROWS*H2];
__device__ float g_pred[(size_t)NROWS*PREDL];

// ---------------- LUT / basis fill ----------------
__global__ void fill_luts(float* __restrict__ basis45, float* __restrict__ cosl,
                          float* __restrict__ sinl) {
    int idx = blockIdx.x * blockDim.x + threadIdx.x;
    if (idx < SEQL) {
        double s, c;
        sincospi((double)(2 * idx) / (double)SEQL, &s, &c);
        cosl[idx] = (float)c;
        sinl[idx] = (float)s;
    }
    if (idx < L2F * NB) {
        int l2 = idx / NB, c = idx % NB;
        float v = 0.f;
        if (c < 23 || (c >= 24 && c < 47)) {
            int g = (c < 23) ? c : (c - 24);
            int a = (g * l2) % L2F;
            double s, cc;
            sincospi((double)(2 * a) / (double)L2F, &s, &cc);
            v = (c < 23) ? (float)cc : (float)(-s);
        }
        basis45[idx] = v;
    }
}

// ---------------- batched transpose (B,R,C) -> (B,C,R) ----------------
__global__ void transpose_batched(const float* __restrict__ in, float* __restrict__ out,
                                  int R, int C) {
    __shared__ float tile[32][33];
    int b = blockIdx.z;
    int c0 = blockIdx.x * 32, r0 = blockIdx.y * 32;
    const float* pin = in + (size_t)b * R * C;
    float* pout = out + (size_t)b * R * C;
    int tx = threadIdx.x, ty = threadIdx.y;
#pragma unroll
    for (int j = 0; j < 32; j += 8) {
        int r = r0 + ty + j, c = c0 + tx;
        if (r < R && c < C) tile[ty + j][tx] = pin[(size_t)r * C + c];
    }
    __syncthreads();
#pragma unroll
    for (int j = 0; j < 32; j += 8) {
        int c = c0 + ty + j, r = r0 + tx;
        if (c < C && r < R) pout[(size_t)c * R + r] = tile[tx][ty + j];
    }
}

// src: (B,C,L) channel-major; out: (B,L,C); if xin != null, out = xin - src^T
__global__ void transpose_sub(const float* __restrict__ src, const float* __restrict__ xin,
                              float* __restrict__ out, int L, int C) {
    __shared__ float tile[32][33];
    int b = blockIdx.z;
    int l0 = blockIdx.x * 32, c0 = blockIdx.y * 32;
    const float* ps = src + (size_t)b * C * L;
#pragma unroll
    for (int j = 0; j < 32; j += 8) {
        int c = c0 + threadIdx.y + j, l = l0 + threadIdx.x;
        if (c < C && l < L) tile[threadIdx.y + j][threadIdx.x] = ps[(size_t)c * L + l];
    }
    __syncthreads();
    size_t ob = (size_t)b * L * C;
#pragma unroll
    for (int j = 0; j < 32; j += 8) {
        int l = l0 + threadIdx.y + j, c = c0 + threadIdx.x;
        if (l < L && c < C) {
            float v = tile[threadIdx.x][threadIdx.y + j];
            if (xin) v = xin[ob + (size_t)l * C + c] - v;
            out[ob + (size_t)l * C + c] = v;
        }
    }
}

// ------- stage-1: per-block 8 xt rows x full DFT45 half-spectrum (fp32) -------
__global__ void __launch_bounds__(256) gemm_s1(
    const float* __restrict__ xt, const float* __restrict__ basis,
    float* __restrict__ spec2) {
    __shared__ float Axt[8][SEQL];
    __shared__ float Bs[L2F][NB];
    const int tid = threadIdx.x;
    const size_t base = (size_t)blockIdx.x * (8 * SEQL);

    {
        const float4* src = reinterpret_cast<const float4*>(xt + base);
        float4* dst = reinterpret_cast<float4*>(&Axt[0][0]);
        for (int i = tid; i < 8 * SEQL / 4; i += 256) dst[i] = src[i];
    }
    {
        const float4* src = reinterpret_cast<const float4*>(basis);
        float4* dst = reinterpret_cast<float4*>(&Bs[0][0]);
        for (int i = tid; i < L2F * NB / 4; i += 256) dst[i] = src[i];
    }
    __syncthreads();

    const int tm = (tid >> 3) * 4;   // CT-row base 0..124
    const int tn = (tid & 7) * 6;    // col base 0..42
    const int orig = tm >> 4;        // original row within block (0..7)
    const int l1b = tm & 15;         // l1 base (0,4,8,12)

    float acc[4][6] = {};
#pragma unroll 15
    for (int k = 0; k < L2F; k++) {
        float4 av = *reinterpret_cast<const float4*>(&Axt[orig][l1b + 16 * k]);
        float2 b0 = *reinterpret_cast<const float2*>(&Bs[k][tn]);
        float2 b1 = *reinterpret_cast<const float2*>(&Bs[k][tn + 2]);
        float2 b2 = *reinterpret_cast<const float2*>(&Bs[k][tn + 4]);
        float a[4] = {av.x, av.y, av.z, av.w};
        float b[6] = {b0.x, b0.y, b1.x, b1.y, b2.x, b2.y};
#pragma unroll
        for (int i = 0; i < 4; i++)
#pragma unroll
            for (int j = 0; j < 6; j++)
                acc[i][j] = fmaf(a[i], b[j], acc[i][j]);
    }

    size_t gmbase = (size_t)blockIdx.x * 128 + tm;
#pragma unroll
    for (int i = 0; i < 4; i++) {
        float* orow = spec2 + (gmbase + i) * NB + tn;
#pragma unroll
        for (int j = 0; j < 6; j += 2)
            *reinterpret_cast<float2*>(&orow[j]) = make_float2(acc[i][j], acc[i][j + 1]);
    }
}

// ------- stage-2 twiddle combine + per-row top-k selection -> coef packs -------
__global__ void __launch_bounds__(128) combine_topk(
    const float* __restrict__ spec2, const int* __restrict__ kptr,
    const float* __restrict__ cosl, const float* __restrict__ sinl,
    float4* __restrict__ coef4, int* __restrict__ coefI) {
    int row = blockIdx.x;
    const float* srow = spec2 + (size_t)row * (L1F * NB);

    __shared__ float2 slut[SEQL];
    __shared__ float2 sS2[L1F][23];        // interleaved (re, im)
    __shared__ float sXre[NFREQ], sXim[NFREQ], sMag[NFREQ];

    int tid = threadIdx.x;
    for (int i = tid; i < SEQL; i += 128) slut[i] = make_float2(cosl[i], sinl[i]);
    for (int i = tid; i < L1F * 23; i += 128) {
        int l1 = i / 23, g = i % 23;
        sS2[l1][g] = make_float2(srow[l1 * NB + g], srow[l1 * NB + 24 + g]);
    }
    __syncthreads();

    // stage 2: X[f] = sum_{l1} S[l1][f%45] * e^{-2pi i f l1 / 720}
    for (int f = tid; f < NFREQ; f += 128) {
        int g = f % L2F;
        int gc = g; float sgn = 1.f;
        if (g >= 23) { gc = L2F - g; sgn = -1.f; }
        float xr = 0.f, xi = 0.f;
        int a = 0;
#pragma unroll
        for (int l1 = 0; l1 < L1F; l1++) {
            float2 w = slut[a];
            float2 s = sS2[l1][gc];
            float sr = s.x;
            float si = sgn * s.y;
            xr = fmaf(sr, w.x, fmaf(si, w.y, xr));
            xi = fmaf(si, w.x, fmaf(-sr, w.y, xi));
            a += f; if (a >= SEQL) a -= SEQL;
        }
        sXre[f] = xr; sXim[f] = xi;
        sMag[f] = xr * xr + xi * xi;
    }
    __syncthreads();

    // warp-private top-k selection
    if (tid < 32) {
        int lane = tid;
        float mag[12];
#pragma unroll
        for (int j = 0; j < 12; j++) {
            int idx = lane + 32 * j;
            mag[j] = (idx < NFREQ) ? sMag[idx] : -1.f;
        }
        int k = *kptr;
        if (k > 32) k = 32;
        if (k < 0) k = 0;
        const float scale = 1.f / (float)SEQL;
        for (int it = 0; it < k; it++) {
            float best = -1.f; int bslot = 0;
#pragma unroll
            for (int j = 0; j < 12; j++)
                if (mag[j] > best) { best = mag[j]; bslot = j; }
            int bidx = lane + 32 * bslot;
#pragma unroll
            for (int o = 16; o > 0; o >>= 1) {
                float ov = __shfl_xor_sync(0xffffffffu, best, o);
                int   oi = __shfl_xor_sync(0xffffffffu, bidx, o);
                if (ov > best || (ov == best && oi < bidx)) { best = ov; bidx = oi; }
            }
            if ((bidx & 31) == lane) {
                int j = bidx >> 5;
                float w = (bidx == 0 || bidx == NFREQ - 1) ? scale : 2.f * scale;
                float2 tw = slut[bidx];
                coef4[(size_t)row * 32 + it] =
                    make_float4(sXre[bidx] * w, sXim[bidx] * w, tw.x, tw.y);
                coefI[(size_t)row * 32 + it] = bidx;
                mag[j] = -2.f;
            }
        }
    }
}

// ------- sparse rotation irfft from coef packs -------
__global__ void __launch_bounds__(256) reconstruct(
    const float4* __restrict__ coef4, const int* __restrict__ coefI,
    const int* __restrict__ kptr,
    const float* __restrict__ cosl, const float* __restrict__ sinl,
    float* __restrict__ filt) {
    int row = blockIdx.x;
    __shared__ float2 slut[SEQL];
    __shared__ float4 sc[32];
    __shared__ int    sf[32];

    int tid = threadIdx.x;
    for (int i = tid; i < SEQL; i += 256) slut[i] = make_float2(cosl[i], sinl[i]);
    int k = *kptr;
    if (k > 32) k = 32;
    if (k < 0) k = 0;
    if (tid < k) {
        sc[tid] = coef4[(size_t)row * 32 + tid];
        sf[tid] = coefI[(size_t)row * 32 + tid];
    }
    __syncthreads();

    float* outp = filt + (size_t)row * SEQL;
    if (tid < 240) {
        int t0 = 3 * tid;
        float acc0 = 0.f, acc1 = 0.f, acc2 = 0.f;
        for (int j = 0; j < k; j++) {
            float4 c4 = sc[j];
            int f = sf[j];
            float r = c4.x, m = c4.y;
            int a0 = (f * t0) % SEQL;
            float2 p0 = slut[a0];
            acc0 = fmaf(r, p0.x, fmaf(-m, p0.y, acc0));
            float2 p1;
            p1.x = fmaf(-p0.y, c4.w, p0.x * c4.z);
            p1.y = fmaf(p0.x, c4.w, p0.y * c4.z);
            acc1 = fmaf(r, p1.x, fmaf(-m, p1.y, acc1));
            float2 p2;
            p2.x = fmaf(-p1.y, c4.w, p1.x * c4.z);
            p2.y = fmaf(p1.x, c4.w, p1.y * c4.z);
            acc2 = fmaf(r, p2.x, fmaf(-m, p2.y, acc2));
        }
        outp[t0 + 0] = acc0;
        outp[t0 + 1] = acc1;
        outp[t0 + 2] = acc2;
    }
}

// ---------------- bf16 helpers ----------------
__device__ __forceinline__ void split_pack_bf16(float e, float o, uint32_t& hi, uint32_t& lo) {
    __nv_bfloat16 he = __float2bfloat16_rn(e);
    __nv_bfloat16 ho = __float2bfloat16_rn(o);
    float re = e - __bfloat162float(he);
    float ro = o - __bfloat162float(ho);
    __nv_bfloat16 le = __float2bfloat16_rn(re);
    __nv_bfloat16 lo2 = __float2bfloat16_rn(ro);
    unsigned short ue = *reinterpret_cast<unsigned short*>(&he);
    unsigned short uo = *reinterpret_cast<unsigned short*>(&ho);
    unsigned short ve = *reinterpret_cast<unsigned short*>(&le);
    unsigned short vo = *reinterpret_cast<unsigned short*>(&lo2);
    hi = ((uint32_t)uo << 16) | ue;
    lo = ((uint32_t)vo << 16) | ve;
}

__device__ __forceinline__ void mma_bf16(float* d, const uint32_t* a, const uint32_t* b) {
    asm volatile(
        "mma.sync.aligned.m16n8k16.row.col.f32.bf16.bf16.f32 "
        "{%0,%1,%2,%3}, {%4,%5,%6,%7}, {%8,%9}, {%0,%1,%2,%3};\n"
        : "+f"(d[0]), "+f"(d[1]), "+f"(d[2]), "+f"(d[3])
        : "r"(a[0]), "r"(a[1]), "r"(a[2]), "r"(a[3]), "r"(b[0]), "r"(b[1]));
}

// ------- tensor-core GEMM: 128M x 64N block, bf16 3-term split, m16n8k16 -------
// z-batched via element strides zA/zB/zCin/zC (grid.z). N guarded.
// MODE 0: +bias ; 1: relu ; 2: relu(+Cin) ; 3: Cin + relu ; 4: Cin + relu(v + bias[row])
template <int MODE>
__global__ void __launch_bounds__(256) gemm_bf(
    const float* __restrict__ A, int lda,
    const float* __restrict__ B, int ldb,
    const float* __restrict__ bias,
    const float* __restrict__ Cin, int ldcin,
    float* __restrict__ C, int ldc,
    int M, int N, int K,
    long zA, long zB, long zCin, long zC) {
    __shared__ uint2 As[8][140];   // [kp][m] (hi, lo)
    __shared__ uint2 Bs[8][76];    // [kp][n]

    const size_t zi = blockIdx.z;
    A += zi * zA; B += zi * zB;
    if (Cin) Cin += zi * zCin;
    C += zi * zC;

    const int tid = threadIdx.x;
    const int m0 = blockIdx.y * 128, n0 = blockIdx.x * 64;
    const int lane = tid & 31, warp = tid >> 5;
    const int wm = warp & 3, wn = warp >> 2;       // 4x2 warp grid
    const int m0w = wm * 32, n0w = wn * 32;        // 32x32 warp tile
    const int kq = lane & 3, gq = lane >> 2;

    const int arow = tid >> 1, ak = (tid & 1) * 8, akp = (tid & 1) * 4;
    const int bkp = tid >> 5, bn2 = (tid & 31) * 2;

    float acc[2][4][4];
#pragma unroll
    for (int i = 0; i < 2; i++)
#pragma unroll
        for (int j = 0; j < 4; j++)
#pragma unroll
            for (int q = 0; q < 4; q++) acc[i][j][q] = 0.f;

    // prefetch first tile
    float4 aP0 = *reinterpret_cast<const float4*>(&A[(size_t)(m0 + arow) * lda + ak]);
    float4 aP1 = *reinterpret_cast<const float4*>(&A[(size_t)(m0 + arow) * lda + ak + 4]);
    float be[2], bo[2];
    {
        const float* B0 = &B[(size_t)(2 * bkp) * ldb];
        const float* B1 = &B[(size_t)(2 * bkp + 1) * ldb];
#pragma unroll
        for (int i = 0; i < 2; i++) {
            int n = n0 + bn2 + i;
            be[i] = (n < N) ? B0[n] : 0.f;
            bo[i] = (n < N) ? B1[n] : 0.f;
        }
    }

    for (int k0 = 0; k0 < K; k0 += 16) {
        {
            float av[8] = {aP0.x, aP0.y, aP0.z, aP0.w, aP1.x, aP1.y, aP1.z, aP1.w};
#pragma unroll
            for (int i = 0; i < 4; i++) {
                uint32_t h, l;
                split_pack_bf16(av[2 * i], av[2 * i + 1], h, l);
                As[akp + i][arow] = make_uint2(h, l);
            }
#pragma unroll
            for (int i = 0; i < 2; i++) {
                uint32_t h, l;
                split_pack_bf16(be[i], bo[i], h, l);
                Bs[bkp][bn2 + i] = make_uint2(h, l);
            }
        }
        __syncthreads();

        if (k0 + 16 < K) {
            aP0 = *reinterpret_cast<const float4*>(&A[(size_t)(m0 + arow) * lda + (k0 + 16 + ak)]);
            aP1 = *reinterpret_cast<const float4*>(&A[(size_t)(m0 + arow) * lda + (k0 + 16 + ak + 4)]);
            const float* B0 = &B[(size_t)(k0 + 16 + 2 * bkp) * ldb];
            const float* B1 = &B[(size_t)(k0 + 16 + 2 * bkp + 1) * ldb];
#pragma unroll
            for (int i = 0; i < 2; i++) {
                int n = n0 + bn2 + i;
                be[i] = (n < N) ? B0[n] : 0.f;
                bo[i] = (n < N) ? B1[n] : 0.f;
            }
        }

        // one k16 MMA sweep
        uint32_t ah[2][4], al[2][4], bh[4][2], bl[4][2];
#pragma unroll
        for (int mi = 0; mi < 2; mi++) {
            int m = m0w + mi * 16 + gq;
            uint2 a00 = As[kq][m],     a01 = As[kq][m + 8];
            uint2 a10 = As[kq + 4][m], a11 = As[kq + 4][m + 8];
            ah[mi][0] = a00.x; ah[mi][1] = a01.x; ah[mi][2] = a10.x; ah[mi][3] = a11.x;
            al[mi][0] = a00.y; al[mi][1] = a01.y; al[mi][2] = a10.y; al[mi][3] = a11.y;
        }
#pragma unroll
        for (int ni = 0; ni < 4; ni++) {
            int n = n0w + ni * 8 + gq;
            uint2 b0 = Bs[kq][n], b1 = Bs[kq + 4][n];
            bh[ni][0] = b0.x; bh[ni][1] = b1.x;
            bl[ni][0] = b0.y; bl[ni][1] = b1.y;
        }
#pragma unroll
        for (int mi = 0; mi < 2; mi++)
#pragma unroll
            for (int ni = 0; ni < 4; ni++) {
                mma_bf16(acc[mi][ni], ah[mi], bh[ni]);
                mma_bf16(acc[mi][ni], al[mi], bh[ni]);
                mma_bf16(acc[mi][ni], ah[mi], bl[ni]);
            }
        __syncthreads();
    }

    // epilogue
#pragma unroll
    for (int mi = 0; mi < 2; mi++)
#pragma unroll
        for (int ni = 0; ni < 4; ni++)
#pragma unroll
            for (int hf = 0; hf < 2; hf++) {
                int gm = m0 + m0w + mi * 16 + gq + hf * 8;
                int gn = n0 + n0w + ni * 8 + kq * 2;
                float v0 = acc[mi][ni][hf * 2 + 0];
                float v1 = acc[mi][ni][hf * 2 + 1];
                bool ok0 = (gn < N), ok1 = (gn + 1 < N);
                if (MODE != 4 && bias) {
                    if (ok0) v0 += bias[gn];
                    if (ok1) v1 += bias[gn + 1];
                }
                if (MODE == 1) { v0 = fmaxf(v0, 0.f); v1 = fmaxf(v1, 0.f); }
                else if (MODE == 2) {
                    if (ok0) v0 += Cin[(size_t)gm * ldcin + gn];
                    if (ok1) v1 += Cin[(size_t)gm * ldcin + gn + 1];
                    v0 = fmaxf(v0, 0.f); v1 = fmaxf(v1, 0.f);
                } else if (MODE == 3) {
                    if (ok0) v0 = Cin[(size_t)gm * ldcin + gn] + fmaxf(v0, 0.f);
                    if (ok1) v1 = Cin[(size_t)gm * ldcin + gn + 1] + fmaxf(v1, 0.f);
                } else if (MODE == 4) {
                    float bb = bias[gm];
                    if (ok0) v0 = Cin[(size_t)gm * ldcin + gn] + fmaxf(v0 + bb, 0.f);
                    if (ok1) v1 = Cin[(size_t)gm * ldcin + gn + 1] + fmaxf(v1 + bb, 0.f);
                }
                if (ok0) C[(size_t)gm * ldc + gn]     = v0;
                if (ok1) C[(size_t)gm * ldc + gn + 1] = v1;
            }
}

// ---------------- host launch ----------------
extern "C" void kernel_launch(void* const* d_in, const int* in_sizes, int n_in,
                              void* d_out, int out_size) {
    const float* x      = (const float*)d_in[0];
    const float* w_freq = (const float*)d_in[1];
    const float* b_freq = (const float*)d_in[2];
    const float* w_all1 = (const float*)d_in[3];
    const float* b_all1 = (const float*)d_in[4];
    const float* w_all2 = (const float*)d_in[5];
    const float* b_all2 = (const float*)d_in[6];
    const float* w_time = (const float*)d_in[7];
    const float* b_time = (const float*)d_in[8];
    const float* w_chan = (const float*)d_in[9];
    const float* b_chan = (const float*)d_in[10];
    const float* w_proj = (const float*)d_in[11];
    const float* b_proj = (const float*)d_in[12];
    const int*   kptr   = (const int*)d_in[13];
    float* out = (float*)d_out;
    size_t half = (size_t)out_size / 2;

    float *basis45, *cosl, *sinl, *xt, *spec2, *filt, *h, *z1, *z, *t, *wchT, *cT, *pred;
    float4* coef4; int* coefI;
    cudaGetSymbolAddress((void**)&basis45, g_basis45);
    cudaGetSymbolAddress((void**)&cosl, g_cosl);
    cudaGetSymbolAddress((void**)&sinl, g_sinl);
    cudaGetSymbolAddress((void**)&xt, g_xt);
    cudaGetSymbolAddress((void**)&spec2, g_spec2);
    cudaGetSymbolAddress((void**)&coef4, g_coef4);
    cudaGetSymbolAddress((void**)&coefI, g_coefI);
    cudaGetSymbolAddress((void**)&filt, g_filt);
    cudaGetSymbolAddress((void**)&h, g_h);
    cudaGetSymbolAddress((void**)&z1, g_z1);
    cudaGetSymbolAddress((void**)&z, g_z);
    cudaGetSymbolAddress((void**)&t, g_t);
    cudaGetSymbolAddress((void**)&wchT, g_wchT);
    cudaGetSymbolAddress((void**)&cT, g_cT);
    cudaGetSymbolAddress((void**)&pred, g_pred);

    dim3 tb(32, 8);

    // 0) twiddle LUTs + DFT45 half-spectrum basis; w_chan transpose
    fill_luts<<<(L2F * NB + 255) / 256, 256>>>(basis45, cosl, sinl);
    transpose_batched<<<dim3(ENC / 32, ENC / 32, 1), tb>>>(w_chan, wchT, ENC, ENC);

    // 1) x (b,L,C) -> xt (b,C,L)
    transpose_batched<<<dim3(ENC / 32, (SEQL + 31) / 32, BATCH), tb>>>(x, xt, SEQL, ENC);

    // 2) stage-1 half-spectra (fp32, fused CT permutation)
    gemm_s1<<<NROWS / 8, 256>>>(xt, basis45, spec2);

    // 3) stage-2 combine + top-k -> coef packs
    combine_topk<<<NROWS, 128>>>(spec2, kptr, cosl, sinl, coef4, coefI);

    // 4) sparse rotation irfft -> filt
    reconstruct<<<NROWS, 256>>>(coef4, coefI, kptr, cosl, sinl, filt);

    // 5) residual = x - filt^T  -> first half of d_out
    transpose_sub<<<dim3((SEQL + 31) / 32, ENC / 32, BATCH), tb>>>(filt, x, out, SEQL, ENC);

    // 6) h = relu(filt @ w_freq + b_freq)   (N=64, K=720)
    gemm_bf<1><<<dim3(1, NROWS / 128), 256>>>(
        filt, SEQL, w_freq, H_FREQ, b_freq, nullptr, 0, h, H_FREQ,
        NROWS, H_FREQ, SEQL, 0, 0, 0, 0);

    // 7) z1 = h @ w_all1[0:64] + b_all1 ; then z1 = relu(xt @ w_all1[64:] + z1)
    gemm_bf<0><<<dim3(H1 / 64, NROWS / 128), 256>>>(
        h, H_FREQ, w_all1, H1, b_all1, nullptr, 0, z1, H1,
        NROWS, H1, H_FREQ, 0, 0, 0, 0);
    gemm_bf<2><<<dim3(H1 / 64, NROWS / 128), 256>>>(
        xt, SEQL, w_all1 + (size_t)H_FREQ * H1, H1, nullptr, z1, H1, z1, H1,
        NROWS, H1, SEQL, 0, 0, 0, 0);

    // 8) z = z1 @ w_all2 + b_all2
    gemm_bf<0><<<dim3(H2 / 64, NROWS / 128), 256>>>(
        z1, H1, w_all2, H2, b_all2, nullptr, 0, z, H2,
        NROWS, H2, H1, 0, 0, 0, 0);

    // 9) t = z + relu(z @ w_time + b_time)
    gemm_bf<3><<<dim3(H2 / 64, NROWS / 128), 256>>>(
        z, H2, w_time, H2, b_time, z, H2, t, H2,
        NROWS, H2, H2, 0, 0, 0, 0);

    // 10) cT = t + relu(wchT @ t + b_chan_row), batched over 64 batches.
    //     cT[b][i][h] = t[b][i][h] + relu(sum_c w_chan[c][i] t[b][c][h] + b_chan[i])
    gemm_bf<4><<<dim3(H2 / 64, ENC / 128, BATCH), 256>>>(
        wchT, ENC, t, H2, b_chan, t, H2, cT, H2,
        ENC, H2, ENC, 0, (long)ENC * H2, (long)ENC * H2, (long)ENC * H2);

    // 11) pred = cT @ w_proj + b_proj   (32768 x 720, K=256)
    gemm_bf<0><<<dim3((PREDL + 63) / 64, NROWS / 128), 256>>>(
        cT, H2, w_proj, PREDL, b_proj, nullptr, 0, pred, PREDL,
        NROWS, PREDL, H2, 0, 0, 0, 0);

    // 12) pred (b,c,l) -> (b,l,c) into second half of d_out
    transpose_sub<<<dim3((PREDL + 31) / 32, ENC / 32, BATCH), tb>>>(
        pred, nullptr, out + half, PREDL, ENC);
}